// round 1
// baseline (speedup 1.0000x reference)
#include <cuda_runtime.h>
#include <math.h>

// Problem constants
#define BB    4
#define NSEQ  2048
#define DIM   1024
#define NH    16
#define HD    64
#define MTOK  (BB*NSEQ)      // 8192 tokens
#define BHN   (BB*NH)        // 64 batch*heads

// ---------------------------------------------------------------------------
// Static device scratch (allocation-free rule: __device__ globals)
// ---------------------------------------------------------------------------
__device__ float g_qkv   [(size_t)MTOK * 3 * DIM];          // 8192 x 3072
__device__ float g_q     [(size_t)BHN * NSEQ * HD];         // [bh, n, hd]
__device__ float g_k     [(size_t)BHN * NSEQ * HD];
__device__ float g_v     [(size_t)BHN * NSEQ * HD];
__device__ float g_logits[(size_t)BHN * NSEQ * NSEQ];       // 1 GiB
__device__ float g_ctx   [(size_t)BHN * NSEQ * HD];         // [bh, n, hd]
__device__ float g_msgin [(size_t)MTOK * DIM];              // [b,n, h*hd]
__device__ float g_msg   [(size_t)MTOK * DIM];              // out-proj result
__device__ float g_hcat  [(size_t)MTOK * 2 * DIM];          // concat
__device__ float g_h     [(size_t)MTOK * 2 * DIM];          // ffn0 out / ln+gelu (in place)
__device__ float g_res   [(size_t)MTOK * DIM];              // ffn3 out

// ---------------------------------------------------------------------------
// Generic tiled SGEMM: C[M,N] = A[M,K] * B + bias
//   TB=false : B is [K,N] row-major (NN)
//   TB=true  : B is [N,K] row-major (C = A * B^T)
// Batched via blockIdx.z with element strides.
// Requirements: M % 128 == 0, K % 8 == 0, lda/ldb multiples of 4.
// N may be arbitrary (guards on B loads and C stores).
// ---------------------------------------------------------------------------
template<bool TB>
__global__ __launch_bounds__(256) void sgemm_kernel(
    const float* __restrict__ A, const float* __restrict__ B,
    const float* __restrict__ bias, float* __restrict__ C,
    int M, int N, int K, int lda, int ldb, int ldc,
    size_t strideA, size_t strideB, size_t strideC)
{
    __shared__ float As[8][128];
    __shared__ float Bs[8][128];
    A += strideA * blockIdx.z;
    B += strideB * blockIdx.z;
    C += strideC * blockIdx.z;

    const int tid  = threadIdx.x;
    const int row0 = blockIdx.y * 128;
    const int col0 = blockIdx.x * 128;
    const int ar   = tid >> 1;          // 0..127
    const int ac   = (tid & 1) << 2;    // 0 or 4
    const int bkr  = tid >> 5;          // 0..7
    const int bc   = (tid & 31) << 2;   // 0..124
    const int ty   = tid >> 4;          // 0..15
    const int tx   = tid & 15;          // 0..15

    float acc[8][8];
    #pragma unroll
    for (int i = 0; i < 8; i++)
        #pragma unroll
        for (int j = 0; j < 8; j++) acc[i][j] = 0.f;

    for (int k0 = 0; k0 < K; k0 += 8) {
        // A tile load (M always multiple of 128 -> no row guard)
        float4 av = *reinterpret_cast<const float4*>(
            A + (size_t)(row0 + ar) * lda + k0 + ac);
        As[ac+0][ar] = av.x; As[ac+1][ar] = av.y;
        As[ac+2][ar] = av.z; As[ac+3][ar] = av.w;

        if (TB) {
            float4 bv = make_float4(0.f, 0.f, 0.f, 0.f);
            if (col0 + ar < N)
                bv = *reinterpret_cast<const float4*>(
                    B + (size_t)(col0 + ar) * ldb + k0 + ac);
            Bs[ac+0][ar] = bv.x; Bs[ac+1][ar] = bv.y;
            Bs[ac+2][ar] = bv.z; Bs[ac+3][ar] = bv.w;
        } else {
            int c = col0 + bc;
            float4 bv = make_float4(0.f, 0.f, 0.f, 0.f);
            if (c + 3 < N) {
                bv = *reinterpret_cast<const float4*>(
                    B + (size_t)(k0 + bkr) * ldb + c);
            } else if (c < N) {
                const float* bp = B + (size_t)(k0 + bkr) * ldb;
                bv.x = bp[c];
                if (c + 1 < N) bv.y = bp[c + 1];
                if (c + 2 < N) bv.z = bp[c + 2];
            }
            Bs[bkr][bc+0] = bv.x; Bs[bkr][bc+1] = bv.y;
            Bs[bkr][bc+2] = bv.z; Bs[bkr][bc+3] = bv.w;
        }
        __syncthreads();

        #pragma unroll
        for (int kk = 0; kk < 8; kk++) {
            float a[8], b[8];
            #pragma unroll
            for (int i = 0; i < 8; i++) a[i] = As[kk][ty * 8 + i];
            #pragma unroll
            for (int j = 0; j < 8; j++) b[j] = Bs[kk][tx * 8 + j];
            #pragma unroll
            for (int i = 0; i < 8; i++)
                #pragma unroll
                for (int j = 0; j < 8; j++)
                    acc[i][j] = fmaf(a[i], b[j], acc[i][j]);
        }
        __syncthreads();
    }

    #pragma unroll
    for (int i = 0; i < 8; i++) {
        int r = row0 + ty * 8 + i;
        #pragma unroll
        for (int j = 0; j < 8; j++) {
            int c = col0 + tx * 8 + j;
            if (c < N)
                C[(size_t)r * ldc + c] = acc[i][j] + (bias ? bias[c] : 0.f);
        }
    }
}

// ---------------------------------------------------------------------------
// RoPE + QKV split: qkv[b,n, h*192 + hd*3 + {0,1,2}] -> q/k/v[bh, n, hd]
// out[2i]   = x[2i]*f0[2i]   - x[2i+1]*f1[2i]
// out[2i+1] = x[2i+1]*f0[2i+1] + x[2i]*f1[2i+1]
// ---------------------------------------------------------------------------
__global__ void rope_split_kernel(const float* __restrict__ qkv,
                                  const float* __restrict__ enc)
{
    size_t idx = (size_t)blockIdx.x * blockDim.x + threadIdx.x;
    const size_t total = (size_t)BB * NH * NSEQ * (HD / 2);
    if (idx >= total) return;
    int pair = idx & 31;             // 0..31
    size_t t = idx >> 5;
    int n = t & (NSEQ - 1); t >>= 11;
    int h = t & (NH - 1);
    int b = (int)(t >> 4);

    const float* src = qkv + ((size_t)(b * NSEQ + n) * (3 * DIM)
                              + h * (HD * 3) + pair * 6);
    float q0 = src[0], k0 = src[1], v0 = src[2];
    float q1 = src[3], k1 = src[4], v1 = src[5];

    const float* e0 = enc + (size_t)n * HD + pair * 2;                 // freqs[0]
    const float* e1 = enc + (size_t)NSEQ * HD + (size_t)n * HD + pair * 2; // freqs[1]
    float f00 = e0[0], f01 = e0[1], f10 = e1[0], f11 = e1[1];

    size_t o = ((size_t)(b * NH + h) * NSEQ + n) * HD + pair * 2;
    g_q[o]     = q0 * f00 - q1 * f10;
    g_q[o + 1] = q1 * f01 + q0 * f11;
    g_k[o]     = k0 * f00 - k1 * f10;
    g_k[o + 1] = k1 * f01 + k0 * f11;
    g_v[o]     = v0;
    g_v[o + 1] = v1;
}

// ---------------------------------------------------------------------------
// Row softmax (in place), applying logit scale. One block per row.
// ---------------------------------------------------------------------------
__global__ __launch_bounds__(256) void softmax_kernel(float* __restrict__ x,
                                                      int n, float scale)
{
    float* p = x + (size_t)blockIdx.x * n;
    const int tid = threadIdx.x;
    __shared__ float s8[8];

    float m = -1e30f;
    for (int i = tid; i < n; i += 256) m = fmaxf(m, p[i] * scale);
    #pragma unroll
    for (int o = 16; o > 0; o >>= 1) m = fmaxf(m, __shfl_xor_sync(~0u, m, o));
    if ((tid & 31) == 0) s8[tid >> 5] = m;
    __syncthreads();
    m = s8[0];
    #pragma unroll
    for (int i = 1; i < 8; i++) m = fmaxf(m, s8[i]);
    __syncthreads();

    float s = 0.f;
    for (int i = tid; i < n; i += 256) {
        float e = __expf(p[i] * scale - m);
        p[i] = e;
        s += e;
    }
    #pragma unroll
    for (int o = 16; o > 0; o >>= 1) s += __shfl_xor_sync(~0u, s, o);
    if ((tid & 31) == 0) s8[tid >> 5] = s;
    __syncthreads();
    s = 0.f;
    #pragma unroll
    for (int i = 0; i < 8; i++) s += s8[i];
    float inv = 1.f / s;
    for (int i = tid; i < n; i += 256) p[i] *= inv;
}

// ---------------------------------------------------------------------------
// ctx[b,h,n,hd] -> msgin[b,n,h*hd]
// ---------------------------------------------------------------------------
__global__ void ctx_transpose_kernel()
{
    size_t idx = (size_t)blockIdx.x * blockDim.x + threadIdx.x;
    const size_t total = (size_t)MTOK * DIM;
    if (idx >= total) return;
    int hd = idx & 63;
    int h  = (idx >> 6) & 15;
    int n  = (idx >> 10) & 2047;
    int b  = (int)(idx >> 21);
    g_msgin[idx] = g_ctx[((size_t)(b * NH + h) * NSEQ + n) * HD + hd];
}

// hcat = [x | msg]
__global__ void concat_kernel(const float* __restrict__ x)
{
    size_t idx = (size_t)blockIdx.x * blockDim.x + threadIdx.x;
    const size_t total = (size_t)MTOK * 2 * DIM;
    if (idx >= total) return;
    size_t m = idx >> 11;
    int c = idx & 2047;
    g_hcat[idx] = (c < DIM) ? x[m * DIM + c] : g_msg[m * DIM + (c - DIM)];
}

// ---------------------------------------------------------------------------
// LayerNorm (over 2048) + exact GELU, in place on g_h. One block per row.
// ---------------------------------------------------------------------------
__global__ __launch_bounds__(256) void ln_gelu_kernel(const float* __restrict__ scale,
                                                      const float* __restrict__ bias)
{
    const int n = 2 * DIM;
    float* p = g_h + (size_t)blockIdx.x * n;
    const int tid = threadIdx.x;
    __shared__ float s8a[8], s8b[8];

    float s = 0.f, sq = 0.f;
    for (int i = tid; i < n; i += 256) {
        float v = p[i];
        s += v;
        sq = fmaf(v, v, sq);
    }
    #pragma unroll
    for (int o = 16; o > 0; o >>= 1) {
        s  += __shfl_xor_sync(~0u, s, o);
        sq += __shfl_xor_sync(~0u, sq, o);
    }
    if ((tid & 31) == 0) { s8a[tid >> 5] = s; s8b[tid >> 5] = sq; }
    __syncthreads();
    s = 0.f; sq = 0.f;
    #pragma unroll
    for (int i = 0; i < 8; i++) { s += s8a[i]; sq += s8b[i]; }
    float mu = s / n;
    float var = sq / n - mu * mu;
    float rstd = rsqrtf(var + 1e-5f);

    for (int i = tid; i < n; i += 256) {
        float v = (p[i] - mu) * rstd * scale[i] + bias[i];
        p[i] = 0.5f * v * (1.f + erff(v * 0.70710678118654752f));
    }
}

// out = x + res
__global__ void residual_kernel(const float* __restrict__ x, float* __restrict__ out)
{
    size_t idx = (size_t)blockIdx.x * blockDim.x + threadIdx.x;
    const size_t total = (size_t)MTOK * DIM;
    if (idx >= total) return;
    out[idx] = x[idx] + g_res[idx];
}

// ---------------------------------------------------------------------------
// Host
// ---------------------------------------------------------------------------
static inline void* sym(const void* s)
{
    void* p = nullptr;
    cudaGetSymbolAddress(&p, s);
    return p;
}

extern "C" void kernel_launch(void* const* d_in, const int* in_sizes, int n_in,
                              void* d_out, int out_size)
{
    const float* x       = (const float*)d_in[0];
    const float* enc     = (const float*)d_in[1];
    const float* Wqkv_w  = (const float*)d_in[2];
    const float* Wqkv_b  = (const float*)d_in[3];
    const float* out_w   = (const float*)d_in[4];
    const float* out_b   = (const float*)d_in[5];
    const float* ffn0_w  = (const float*)d_in[6];
    const float* ffn0_b  = (const float*)d_in[7];
    const float* ln_s    = (const float*)d_in[8];
    const float* ln_b    = (const float*)d_in[9];
    const float* ffn3_w  = (const float*)d_in[10];
    const float* ffn3_b  = (const float*)d_in[11];
    float* out = (float*)d_out;

    float* qkv    = (float*)sym(g_qkv);
    float* q      = (float*)sym(g_q);
    float* k      = (float*)sym(g_k);
    float* v      = (float*)sym(g_v);
    float* logits = (float*)sym(g_logits);
    float* ctx    = (float*)sym(g_ctx);
    float* msgin  = (float*)sym(g_msgin);
    float* msg    = (float*)sym(g_msg);
    float* hcat   = (float*)sym(g_hcat);
    float* hbuf   = (float*)sym(g_h);
    float* res    = (float*)sym(g_res);

    // 1. QKV projection: [8192,1024] x [1024,3072] + b
    sgemm_kernel<false><<<dim3(3 * DIM / 128, MTOK / 128, 1), 256>>>(
        x, Wqkv_w, Wqkv_b, qkv, MTOK, 3 * DIM, DIM, DIM, 3 * DIM, 3 * DIM, 0, 0, 0);

    // 2. RoPE + split into q/k/v [bh,n,hd]
    {
        size_t total = (size_t)BB * NH * NSEQ * (HD / 2);
        rope_split_kernel<<<(unsigned)((total + 255) / 256), 256>>>(qkv, enc);
    }

    // 3. logits = Q * K^T   (batched NT, M=N=2048, K=64, batch=64)
    sgemm_kernel<true><<<dim3(NSEQ / 128, NSEQ / 128, BHN), 256>>>(
        q, k, nullptr, logits, NSEQ, NSEQ, HD, HD, HD, NSEQ,
        (size_t)NSEQ * HD, (size_t)NSEQ * HD, (size_t)NSEQ * NSEQ);

    // 4. softmax rows (scale = 1/sqrt(64))
    softmax_kernel<<<BHN * NSEQ, 256>>>(logits, NSEQ, 0.125f);

    // 5. ctx = P * V   (batched NN, M=2048, N=64, K=2048)
    sgemm_kernel<false><<<dim3(1, NSEQ / 128, BHN), 256>>>(
        logits, v, nullptr, ctx, NSEQ, HD, NSEQ, NSEQ, HD, HD,
        (size_t)NSEQ * NSEQ, (size_t)NSEQ * HD, (size_t)NSEQ * HD);

    // 6. transpose to [b,n,h*hd]
    {
        size_t total = (size_t)MTOK * DIM;
        ctx_transpose_kernel<<<(unsigned)((total + 255) / 256), 256>>>();
    }

    // 7. out projection
    sgemm_kernel<false><<<dim3(DIM / 128, MTOK / 128, 1), 256>>>(
        msgin, out_w, out_b, msg, MTOK, DIM, DIM, DIM, DIM, DIM, 0, 0, 0);

    // 8. concat [x | msg]
    {
        size_t total = (size_t)MTOK * 2 * DIM;
        concat_kernel<<<(unsigned)((total + 255) / 256), 256>>>(x);
    }

    // 9. FFN0: [8192,2048] x [2048,2048] + b
    sgemm_kernel<false><<<dim3(2 * DIM / 128, MTOK / 128, 1), 256>>>(
        hcat, ffn0_w, ffn0_b, hbuf, MTOK, 2 * DIM, 2 * DIM,
        2 * DIM, 2 * DIM, 2 * DIM, 0, 0, 0);

    // 10. LayerNorm + GELU (in place)
    ln_gelu_kernel<<<MTOK, 256>>>(ln_s, ln_b);

    // 11. FFN3: [8192,2048] x [2048,1024] + b
    sgemm_kernel<false><<<dim3(DIM / 128, MTOK / 128, 1), 256>>>(
        hbuf, ffn3_w, ffn3_b, res, MTOK, DIM, 2 * DIM,
        2 * DIM, DIM, DIM, 0, 0, 0);

    // 12. residual
    {
        size_t total = (size_t)MTOK * DIM;
        residual_kernel<<<(unsigned)((total + 255) / 256), 256>>>(x, out);
    }
}

// round 2
// speedup vs baseline: 2.5100x; 2.5100x over previous
#include <cuda_runtime.h>
#include <math.h>

// Problem constants
#define BB    4
#define NSEQ  2048
#define DIM   1024
#define NH    16
#define HD    64
#define MTOK  (BB*NSEQ)      // 8192 tokens
#define BHN   (BB*NH)        // 64 batch*heads

// ---------------------------------------------------------------------------
// Static device scratch
// ---------------------------------------------------------------------------
__device__ float g_qkv   [(size_t)MTOK * 3 * DIM];
__device__ float g_q     [(size_t)BHN * NSEQ * HD];
__device__ float g_k     [(size_t)BHN * NSEQ * HD];
__device__ float g_v     [(size_t)BHN * NSEQ * HD];
__device__ float g_logits[(size_t)BHN * NSEQ * NSEQ];       // 1 GiB
__device__ float g_ctx   [(size_t)BHN * NSEQ * HD];
__device__ float g_msgin [(size_t)MTOK * DIM];
__device__ float g_msg   [(size_t)MTOK * DIM];
__device__ float g_hcat  [(size_t)MTOK * 2 * DIM];
__device__ float g_h     [(size_t)MTOK * 2 * DIM];

// ---------------------------------------------------------------------------
// tf32 helpers
// ---------------------------------------------------------------------------
__device__ __forceinline__ unsigned f2tf(float f) {
    unsigned r;
    asm("cvt.rna.tf32.f32 %0, %1;" : "=r"(r) : "f"(f));
    return r;
}

__device__ __forceinline__ void mma8(float c[4],
    unsigned a0, unsigned a1, unsigned a2, unsigned a3,
    unsigned b0, unsigned b1)
{
    asm volatile(
        "mma.sync.aligned.m16n8k8.row.col.f32.tf32.tf32.f32 "
        "{%0,%1,%2,%3}, {%4,%5,%6,%7}, {%8,%9}, {%0,%1,%2,%3};"
        : "+f"(c[0]), "+f"(c[1]), "+f"(c[2]), "+f"(c[3])
        : "r"(a0), "r"(a1), "r"(a2), "r"(a3), "r"(b0), "r"(b1));
}

// ---------------------------------------------------------------------------
// tf32 tensor-core GEMM: C[M,N] = A[M,K] * B (+bias) (+resid)
//   TB=false : B is [K,N] row-major.  TB=true : B is [N,K] (C = A*B^T)
// BM=128, BK=16 fixed. BN / warp grid via template.
// Requires: M%128==0, N%BN==0, K%16==0, lda/ldb%4==0, ldc%2==0.
// Batched via blockIdx.z.
// ---------------------------------------------------------------------------
template<int BN, int WM, int WN, bool TB>
__global__ __launch_bounds__(256) void mma_gemm(
    const float* __restrict__ A, const float* __restrict__ B,
    const float* __restrict__ bias, const float* __restrict__ resid,
    float* __restrict__ C,
    int K, int lda, int ldb, int ldc,
    size_t sA, size_t sB, size_t sC)
{
    constexpr int BM  = 128, BK = 16;
    constexpr int SAS = BM + 8;              // stride ≡ 8 (mod 32): conflict-free frags
    constexpr int SBS = BN + 8;
    constexpr int MI  = BM / WM / 16;        // m16 tiles per warp
    constexpr int NI  = BN / WN / 8;         // n8 tiles per warp
    constexpr int NA4 = (BM * BK) / 4 / 256; // float4 per thread, A tile
    constexpr int NB4 = (BN * BK) / 4 / 256;

    __shared__ unsigned As[2][BK][SAS];
    __shared__ unsigned Bs[2][BK][SBS];

    A += sA * blockIdx.z; B += sB * blockIdx.z; C += sC * blockIdx.z;
    const int tid  = threadIdx.x;
    const int warp = tid >> 5, lane = tid & 31;
    const int g    = lane >> 2, tg = lane & 3;
    const int wm   = warp % WM, wn = warp / WM;
    const int row0 = blockIdx.y * BM, col0 = blockIdx.x * BN;

    float acc[MI][NI][4] = {};

    auto loadA = [&](int k0, float4 va[NA4]) {
        #pragma unroll
        for (int i = 0; i < NA4; i++) {
            int idx = tid + i * 256;                       // 512 f4: row=idx>>2
            va[i] = *(const float4*)(A + (size_t)(row0 + (idx >> 2)) * lda
                                       + k0 + (idx & 3) * 4);
        }
    };
    auto storeA = [&](int buf, float4 va[NA4]) {
        #pragma unroll
        for (int i = 0; i < NA4; i++) {
            int idx = tid + i * 256;
            int r = idx >> 2, kc = (idx & 3) * 4;
            As[buf][kc + 0][r] = f2tf(va[i].x);
            As[buf][kc + 1][r] = f2tf(va[i].y);
            As[buf][kc + 2][r] = f2tf(va[i].z);
            As[buf][kc + 3][r] = f2tf(va[i].w);
        }
    };
    auto loadB = [&](int k0, float4 vb[NB4]) {
        #pragma unroll
        for (int i = 0; i < NB4; i++) {
            int idx = tid + i * 256;
            if (TB) {
                vb[i] = *(const float4*)(B + (size_t)(col0 + (idx >> 2)) * ldb
                                           + k0 + (idx & 3) * 4);
            } else {
                constexpr int BQ = BN / 4;
                vb[i] = *(const float4*)(B + (size_t)(k0 + idx / BQ) * ldb
                                           + col0 + (idx % BQ) * 4);
            }
        }
    };
    auto storeB = [&](int buf, float4 vb[NB4]) {
        #pragma unroll
        for (int i = 0; i < NB4; i++) {
            int idx = tid + i * 256;
            if (TB) {
                int n = idx >> 2, kc = (idx & 3) * 4;
                Bs[buf][kc + 0][n] = f2tf(vb[i].x);
                Bs[buf][kc + 1][n] = f2tf(vb[i].y);
                Bs[buf][kc + 2][n] = f2tf(vb[i].z);
                Bs[buf][kc + 3][n] = f2tf(vb[i].w);
            } else {
                constexpr int BQ = BN / 4;
                int kr = idx / BQ, nc = (idx % BQ) * 4;
                Bs[buf][kr][nc + 0] = f2tf(vb[i].x);
                Bs[buf][kr][nc + 1] = f2tf(vb[i].y);
                Bs[buf][kr][nc + 2] = f2tf(vb[i].z);
                Bs[buf][kr][nc + 3] = f2tf(vb[i].w);
            }
        }
    };
    auto compute = [&](int buf) {
        #pragma unroll
        for (int ks = 0; ks < 2; ks++) {
            unsigned af[MI][4], bf[NI][2];
            #pragma unroll
            for (int mi = 0; mi < MI; mi++) {
                int mb = wm * (BM / WM) + mi * 16;
                af[mi][0] = As[buf][ks * 8 + tg][mb + g];
                af[mi][1] = As[buf][ks * 8 + tg][mb + g + 8];
                af[mi][2] = As[buf][ks * 8 + tg + 4][mb + g];
                af[mi][3] = As[buf][ks * 8 + tg + 4][mb + g + 8];
            }
            #pragma unroll
            for (int ni = 0; ni < NI; ni++) {
                int nb = wn * (BN / WN) + ni * 8;
                bf[ni][0] = Bs[buf][ks * 8 + tg][nb + g];
                bf[ni][1] = Bs[buf][ks * 8 + tg + 4][nb + g];
            }
            #pragma unroll
            for (int mi = 0; mi < MI; mi++)
                #pragma unroll
                for (int ni = 0; ni < NI; ni++)
                    mma8(acc[mi][ni], af[mi][0], af[mi][1], af[mi][2], af[mi][3],
                         bf[ni][0], bf[ni][1]);
        }
    };

    float4 va[NA4], vb[NB4];
    loadA(0, va); loadB(0, vb);
    storeA(0, va); storeB(0, vb);
    __syncthreads();
    int buf = 0;
    for (int k0 = BK; k0 < K; k0 += BK) {
        loadA(k0, va); loadB(k0, vb);   // prefetch next tile (overlaps mma)
        compute(buf);
        __syncthreads();
        storeA(buf ^ 1, va); storeB(buf ^ 1, vb);
        buf ^= 1;
        __syncthreads();
    }
    compute(buf);

    // Epilogue
    #pragma unroll
    for (int mi = 0; mi < MI; mi++) {
        int rb = row0 + wm * (BM / WM) + mi * 16 + g;
        #pragma unroll
        for (int ni = 0; ni < NI; ni++) {
            int cb = col0 + wn * (BN / WN) + ni * 8 + 2 * tg;
            float b0v = bias ? bias[cb]     : 0.f;
            float b1v = bias ? bias[cb + 1] : 0.f;
            float2 v0 = make_float2(acc[mi][ni][0] + b0v, acc[mi][ni][1] + b1v);
            float2 v1 = make_float2(acc[mi][ni][2] + b0v, acc[mi][ni][3] + b1v);
            if (resid) {
                v0.x += resid[(size_t)rb * ldc + cb];
                v0.y += resid[(size_t)rb * ldc + cb + 1];
                v1.x += resid[(size_t)(rb + 8) * ldc + cb];
                v1.y += resid[(size_t)(rb + 8) * ldc + cb + 1];
            }
            *(float2*)(C + (size_t)rb * ldc + cb)       = v0;
            *(float2*)(C + (size_t)(rb + 8) * ldc + cb) = v1;
        }
    }
}

// ---------------------------------------------------------------------------
// RoPE + QKV split
// ---------------------------------------------------------------------------
__global__ void rope_split_kernel(const float* __restrict__ qkv,
                                  const float* __restrict__ enc)
{
    size_t idx = (size_t)blockIdx.x * blockDim.x + threadIdx.x;
    const size_t total = (size_t)BB * NH * NSEQ * (HD / 2);
    if (idx >= total) return;
    int pair = idx & 31;
    size_t t = idx >> 5;
    int n = t & (NSEQ - 1); t >>= 11;
    int h = t & (NH - 1);
    int b = (int)(t >> 4);

    const float* src = qkv + ((size_t)(b * NSEQ + n) * (3 * DIM)
                              + h * (HD * 3) + pair * 6);
    float q0 = src[0], k0 = src[1], v0 = src[2];
    float q1 = src[3], k1 = src[4], v1 = src[5];

    const float* e0 = enc + (size_t)n * HD + pair * 2;
    const float* e1 = enc + (size_t)NSEQ * HD + (size_t)n * HD + pair * 2;
    float f00 = e0[0], f01 = e0[1], f10 = e1[0], f11 = e1[1];

    size_t o = ((size_t)(b * NH + h) * NSEQ + n) * HD + pair * 2;
    g_q[o]     = q0 * f00 - q1 * f10;
    g_q[o + 1] = q1 * f01 + q0 * f11;
    g_k[o]     = k0 * f00 - k1 * f10;
    g_k[o + 1] = k1 * f01 + k0 * f11;
    g_v[o]     = v0;
    g_v[o + 1] = v1;
}

// ---------------------------------------------------------------------------
// Row softmax (in place), with logit scale.
// ---------------------------------------------------------------------------
__global__ __launch_bounds__(256) void softmax_kernel(float* __restrict__ x,
                                                      int n, float scale)
{
    float* p = x + (size_t)blockIdx.x * n;
    const int tid = threadIdx.x;
    __shared__ float s8[8];

    float m = -1e30f;
    for (int i = tid; i < n; i += 256) m = fmaxf(m, p[i] * scale);
    #pragma unroll
    for (int o = 16; o > 0; o >>= 1) m = fmaxf(m, __shfl_xor_sync(~0u, m, o));
    if ((tid & 31) == 0) s8[tid >> 5] = m;
    __syncthreads();
    m = s8[0];
    #pragma unroll
    for (int i = 1; i < 8; i++) m = fmaxf(m, s8[i]);
    __syncthreads();

    float s = 0.f;
    for (int i = tid; i < n; i += 256) {
        float e = __expf(p[i] * scale - m);
        p[i] = e;
        s += e;
    }
    #pragma unroll
    for (int o = 16; o > 0; o >>= 1) s += __shfl_xor_sync(~0u, s, o);
    if ((tid & 31) == 0) s8[tid >> 5] = s;
    __syncthreads();
    s = 0.f;
    #pragma unroll
    for (int i = 0; i < 8; i++) s += s8[i];
    float inv = 1.f / s;
    for (int i = tid; i < n; i += 256) p[i] *= inv;
}

// ctx[b,h,n,hd] -> msgin[b,n,h*hd]
__global__ void ctx_transpose_kernel()
{
    size_t idx = (size_t)blockIdx.x * blockDim.x + threadIdx.x;
    const size_t total = (size_t)MTOK * DIM;
    if (idx >= total) return;
    int hd = idx & 63;
    int h  = (idx >> 6) & 15;
    int n  = (idx >> 10) & 2047;
    int b  = (int)(idx >> 21);
    g_msgin[idx] = g_ctx[((size_t)(b * NH + h) * NSEQ + n) * HD + hd];
}

// hcat = [x | msg]
__global__ void concat_kernel(const float* __restrict__ x)
{
    size_t idx = (size_t)blockIdx.x * blockDim.x + threadIdx.x;
    const size_t total = (size_t)MTOK * 2 * DIM;
    if (idx >= total) return;
    size_t m = idx >> 11;
    int c = idx & 2047;
    g_hcat[idx] = (c < DIM) ? x[m * DIM + c] : g_msg[m * DIM + (c - DIM)];
}

// LayerNorm (2048) + exact GELU, in place on g_h.
__global__ __launch_bounds__(256) void ln_gelu_kernel(const float* __restrict__ scale,
                                                      const float* __restrict__ bias)
{
    const int n = 2 * DIM;
    float* p = g_h + (size_t)blockIdx.x * n;
    const int tid = threadIdx.x;
    __shared__ float s8a[8], s8b[8];

    float s = 0.f, sq = 0.f;
    for (int i = tid; i < n; i += 256) {
        float v = p[i];
        s += v;
        sq = fmaf(v, v, sq);
    }
    #pragma unroll
    for (int o = 16; o > 0; o >>= 1) {
        s  += __shfl_xor_sync(~0u, s, o);
        sq += __shfl_xor_sync(~0u, sq, o);
    }
    if ((tid & 31) == 0) { s8a[tid >> 5] = s; s8b[tid >> 5] = sq; }
    __syncthreads();
    s = 0.f; sq = 0.f;
    #pragma unroll
    for (int i = 0; i < 8; i++) { s += s8a[i]; sq += s8b[i]; }
    float mu = s / n;
    float var = sq / n - mu * mu;
    float rstd = rsqrtf(var + 1e-5f);

    for (int i = tid; i < n; i += 256) {
        float v = (p[i] - mu) * rstd * scale[i] + bias[i];
        p[i] = 0.5f * v * (1.f + erff(v * 0.70710678118654752f));
    }
}

// ---------------------------------------------------------------------------
// Host
// ---------------------------------------------------------------------------
static inline void* sym(const void* s)
{
    void* p = nullptr;
    cudaGetSymbolAddress(&p, s);
    return p;
}

extern "C" void kernel_launch(void* const* d_in, const int* in_sizes, int n_in,
                              void* d_out, int out_size)
{
    const float* x       = (const float*)d_in[0];
    const float* enc     = (const float*)d_in[1];
    const float* Wqkv_w  = (const float*)d_in[2];
    const float* Wqkv_b  = (const float*)d_in[3];
    const float* out_w   = (const float*)d_in[4];
    const float* out_b   = (const float*)d_in[5];
    const float* ffn0_w  = (const float*)d_in[6];
    const float* ffn0_b  = (const float*)d_in[7];
    const float* ln_s    = (const float*)d_in[8];
    const float* ln_b    = (const float*)d_in[9];
    const float* ffn3_w  = (const float*)d_in[10];
    const float* ffn3_b  = (const float*)d_in[11];
    float* out = (float*)d_out;

    float* qkv    = (float*)sym(g_qkv);
    float* q      = (float*)sym(g_q);
    float* k      = (float*)sym(g_k);
    float* v      = (float*)sym(g_v);
    float* logits = (float*)sym(g_logits);
    float* ctx    = (float*)sym(g_ctx);
    float* msgin  = (float*)sym(g_msgin);
    float* msg    = (float*)sym(g_msg);
    float* hcat   = (float*)sym(g_hcat);
    float* hbuf   = (float*)sym(g_h);

    // 1. QKV projection: [8192,1024] x [1024,3072] + b
    mma_gemm<128, 2, 4, false><<<dim3(3 * DIM / 128, MTOK / 128, 1), 256>>>(
        x, Wqkv_w, Wqkv_b, nullptr, qkv, DIM, DIM, 3 * DIM, 3 * DIM, 0, 0, 0);

    // 2. RoPE + split
    {
        size_t total = (size_t)BB * NH * NSEQ * (HD / 2);
        rope_split_kernel<<<(unsigned)((total + 255) / 256), 256>>>(qkv, enc);
    }

    // 3. logits = Q * K^T (batched NT, M=N=2048, K=64, batch=64)
    mma_gemm<128, 2, 4, true><<<dim3(NSEQ / 128, NSEQ / 128, BHN), 256>>>(
        q, k, nullptr, nullptr, logits, HD, HD, HD, NSEQ,
        (size_t)NSEQ * HD, (size_t)NSEQ * HD, (size_t)NSEQ * NSEQ);

    // 4. softmax (scale = 1/sqrt(64))
    softmax_kernel<<<BHN * NSEQ, 256>>>(logits, NSEQ, 0.125f);

    // 5. ctx = P * V (batched NN, M=2048, N=64, K=2048)
    mma_gemm<64, 4, 2, false><<<dim3(1, NSEQ / 128, BHN), 256>>>(
        logits, v, nullptr, nullptr, ctx, NSEQ, NSEQ, HD, HD,
        (size_t)NSEQ * NSEQ, (size_t)NSEQ * HD, (size_t)NSEQ * HD);

    // 6. transpose to [b,n,h*hd]
    {
        size_t total = (size_t)MTOK * DIM;
        ctx_transpose_kernel<<<(unsigned)((total + 255) / 256), 256>>>();
    }

    // 7. out projection
    mma_gemm<128, 2, 4, false><<<dim3(DIM / 128, MTOK / 128, 1), 256>>>(
        msgin, out_w, out_b, nullptr, msg, DIM, DIM, DIM, DIM, 0, 0, 0);

    // 8. concat [x | msg]
    {
        size_t total = (size_t)MTOK * 2 * DIM;
        concat_kernel<<<(unsigned)((total + 255) / 256), 256>>>(x);
    }

    // 9. FFN0: [8192,2048] x [2048,2048] + b
    mma_gemm<128, 2, 4, false><<<dim3(2 * DIM / 128, MTOK / 128, 1), 256>>>(
        hcat, ffn0_w, ffn0_b, nullptr, hbuf, 2 * DIM, 2 * DIM, 2 * DIM, 2 * DIM,
        0, 0, 0);

    // 10. LayerNorm + GELU (in place)
    ln_gelu_kernel<<<MTOK, 256>>>(ln_s, ln_b);

    // 11. FFN3 + residual fused: out = hbuf*W3 + b3 + x
    mma_gemm<128, 2, 4, false><<<dim3(DIM / 128, MTOK / 128, 1), 256>>>(
        hbuf, ffn3_w, ffn3_b, x, out, 2 * DIM, 2 * DIM, DIM, DIM, 0, 0, 0);
}

// round 3
// speedup vs baseline: 3.1424x; 1.2520x over previous
#include <cuda_runtime.h>
#include <math.h>

// Problem constants
#define BB    4
#define NSEQ  2048
#define DIM   1024
#define NH    16
#define HD    64
#define MTOK  (BB*NSEQ)      // 8192 tokens
#define BHN   (BB*NH)        // 64 batch*heads

// ---------------------------------------------------------------------------
// Static device scratch
// ---------------------------------------------------------------------------
__device__ float g_qkv  [(size_t)MTOK * 3 * DIM];
__device__ float g_q    [(size_t)BHN * NSEQ * HD];
__device__ float g_k    [(size_t)BHN * NSEQ * HD];
__device__ float g_v    [(size_t)BHN * NSEQ * HD];
__device__ float g_msgin[(size_t)MTOK * DIM];   // flash output, [b,n,h*hd]
__device__ float g_msg  [(size_t)MTOK * DIM];
__device__ float g_h    [(size_t)MTOK * 2 * DIM];

// ---------------------------------------------------------------------------
// tf32 helpers
// ---------------------------------------------------------------------------
__device__ __forceinline__ unsigned f2tf(float f) {
    unsigned r;
    asm("cvt.rna.tf32.f32 %0, %1;" : "=r"(r) : "f"(f));
    return r;
}

__device__ __forceinline__ void mma8(float c[4],
    unsigned a0, unsigned a1, unsigned a2, unsigned a3,
    unsigned b0, unsigned b1)
{
    asm volatile(
        "mma.sync.aligned.m16n8k8.row.col.f32.tf32.tf32.f32 "
        "{%0,%1,%2,%3}, {%4,%5,%6,%7}, {%8,%9}, {%0,%1,%2,%3};"
        : "+f"(c[0]), "+f"(c[1]), "+f"(c[2]), "+f"(c[3])
        : "r"(a0), "r"(a1), "r"(a2), "r"(a3), "r"(b0), "r"(b1));
}

// ---------------------------------------------------------------------------
// tf32 tensor-core GEMM: C[M,N] = [A | A2][M,K] * B (+bias) (+resid)
//   A covers k < K1 (lda), A2 covers k >= K1 (lda2). A2 may be null (K1=K).
//   TB=false : B is [K,N] row-major.  TB=true : B is [N,K] (C = A*B^T)
// BM=128, BK=16. Requires M%128==0, N%BN==0, K%16==0, K1%16==0.
// ---------------------------------------------------------------------------
template<int BN, int WM, int WN, bool TB>
__global__ __launch_bounds__(256) void mma_gemm(
    const float* __restrict__ A, const float* __restrict__ A2,
    const float* __restrict__ B,
    const float* __restrict__ bias, const float* __restrict__ resid,
    float* __restrict__ C,
    int K, int K1, int lda, int lda2, int ldb, int ldc,
    size_t sA, size_t sB, size_t sC)
{
    constexpr int BM  = 128, BK = 16;
    constexpr int SAS = BM + 8;
    constexpr int SBS = BN + 8;
    constexpr int MI  = BM / WM / 16;
    constexpr int NI  = BN / WN / 8;
    constexpr int NA4 = (BM * BK) / 4 / 256;
    constexpr int NB4 = (BN * BK) / 4 / 256;

    __shared__ unsigned As[2][BK][SAS];
    __shared__ unsigned Bs[2][BK][SBS];

    A += sA * blockIdx.z; B += sB * blockIdx.z; C += sC * blockIdx.z;
    const int tid  = threadIdx.x;
    const int warp = tid >> 5, lane = tid & 31;
    const int g    = lane >> 2, tg = lane & 3;
    const int wm   = warp % WM, wn = warp / WM;
    const int row0 = blockIdx.y * BM, col0 = blockIdx.x * BN;

    float acc[MI][NI][4] = {};

    auto loadA = [&](int k0, float4 va[NA4]) {
        const float* src = A;
        int kk = k0, ld = lda;
        if (A2 && k0 >= K1) { src = A2; kk = k0 - K1; ld = lda2; }
        #pragma unroll
        for (int i = 0; i < NA4; i++) {
            int idx = tid + i * 256;
            va[i] = *(const float4*)(src + (size_t)(row0 + (idx >> 2)) * ld
                                       + kk + (idx & 3) * 4);
        }
    };
    auto storeA = [&](int buf, float4 va[NA4]) {
        #pragma unroll
        for (int i = 0; i < NA4; i++) {
            int idx = tid + i * 256;
            int r = idx >> 2, kc = (idx & 3) * 4;
            As[buf][kc + 0][r] = f2tf(va[i].x);
            As[buf][kc + 1][r] = f2tf(va[i].y);
            As[buf][kc + 2][r] = f2tf(va[i].z);
            As[buf][kc + 3][r] = f2tf(va[i].w);
        }
    };
    auto loadB = [&](int k0, float4 vb[NB4]) {
        #pragma unroll
        for (int i = 0; i < NB4; i++) {
            int idx = tid + i * 256;
            if (TB) {
                vb[i] = *(const float4*)(B + (size_t)(col0 + (idx >> 2)) * ldb
                                           + k0 + (idx & 3) * 4);
            } else {
                constexpr int BQ = BN / 4;
                vb[i] = *(const float4*)(B + (size_t)(k0 + idx / BQ) * ldb
                                           + col0 + (idx % BQ) * 4);
            }
        }
    };
    auto storeB = [&](int buf, float4 vb[NB4]) {
        #pragma unroll
        for (int i = 0; i < NB4; i++) {
            int idx = tid + i * 256;
            if (TB) {
                int n = idx >> 2, kc = (idx & 3) * 4;
                Bs[buf][kc + 0][n] = f2tf(vb[i].x);
                Bs[buf][kc + 1][n] = f2tf(vb[i].y);
                Bs[buf][kc + 2][n] = f2tf(vb[i].z);
                Bs[buf][kc + 3][n] = f2tf(vb[i].w);
            } else {
                constexpr int BQ = BN / 4;
                int kr = idx / BQ, nc = (idx % BQ) * 4;
                Bs[buf][kr][nc + 0] = f2tf(vb[i].x);
                Bs[buf][kr][nc + 1] = f2tf(vb[i].y);
                Bs[buf][kr][nc + 2] = f2tf(vb[i].z);
                Bs[buf][kr][nc + 3] = f2tf(vb[i].w);
            }
        }
    };
    auto compute = [&](int buf) {
        #pragma unroll
        for (int ks = 0; ks < 2; ks++) {
            unsigned af[MI][4], bf[NI][2];
            #pragma unroll
            for (int mi = 0; mi < MI; mi++) {
                int mb = wm * (BM / WM) + mi * 16;
                af[mi][0] = As[buf][ks * 8 + tg][mb + g];
                af[mi][1] = As[buf][ks * 8 + tg][mb + g + 8];
                af[mi][2] = As[buf][ks * 8 + tg + 4][mb + g];
                af[mi][3] = As[buf][ks * 8 + tg + 4][mb + g + 8];
            }
            #pragma unroll
            for (int ni = 0; ni < NI; ni++) {
                int nb = wn * (BN / WN) + ni * 8;
                bf[ni][0] = Bs[buf][ks * 8 + tg][nb + g];
                bf[ni][1] = Bs[buf][ks * 8 + tg + 4][nb + g];
            }
            #pragma unroll
            for (int mi = 0; mi < MI; mi++)
                #pragma unroll
                for (int ni = 0; ni < NI; ni++)
                    mma8(acc[mi][ni], af[mi][0], af[mi][1], af[mi][2], af[mi][3],
                         bf[ni][0], bf[ni][1]);
        }
    };

    float4 va[NA4], vb[NB4];
    loadA(0, va); loadB(0, vb);
    storeA(0, va); storeB(0, vb);
    __syncthreads();
    int buf = 0;
    for (int k0 = BK; k0 < K; k0 += BK) {
        loadA(k0, va); loadB(k0, vb);
        compute(buf);
        __syncthreads();
        storeA(buf ^ 1, va); storeB(buf ^ 1, vb);
        buf ^= 1;
        __syncthreads();
    }
    compute(buf);

    #pragma unroll
    for (int mi = 0; mi < MI; mi++) {
        int rb = row0 + wm * (BM / WM) + mi * 16 + g;
        #pragma unroll
        for (int ni = 0; ni < NI; ni++) {
            int cb = col0 + wn * (BN / WN) + ni * 8 + 2 * tg;
            float b0v = bias ? bias[cb]     : 0.f;
            float b1v = bias ? bias[cb + 1] : 0.f;
            float2 v0 = make_float2(acc[mi][ni][0] + b0v, acc[mi][ni][1] + b1v);
            float2 v1 = make_float2(acc[mi][ni][2] + b0v, acc[mi][ni][3] + b1v);
            if (resid) {
                v0.x += resid[(size_t)rb * ldc + cb];
                v0.y += resid[(size_t)rb * ldc + cb + 1];
                v1.x += resid[(size_t)(rb + 8) * ldc + cb];
                v1.y += resid[(size_t)(rb + 8) * ldc + cb + 1];
            }
            *(float2*)(C + (size_t)rb * ldc + cb)       = v0;
            *(float2*)(C + (size_t)(rb + 8) * ldc + cb) = v1;
        }
    }
}

// ---------------------------------------------------------------------------
// Flash attention, tf32 mma, HD=64.
// Grid: (16 q-tiles, 64 bh). Block: 256 threads = 8 warps; warp w owns
// 16 q rows. Q frags live in registers; K/V tiles in smem; P goes through a
// warp-private smem tile to re-shape C-layout -> A-layout.
// Writes context directly to msgin[b, n, h*64 + hd].
// smem word layout (all strides == 4 mod 32 => conflict-free frag access):
//   [0, 16896)      Qs[128][68] (prologue) / Ps: per-warp 16 x 132
//   [16896, 25600)  Ks[128][68]   (K tile, [kv][hd])
//   [25600, 34304)  Vs[128][68]   (V tile, [kv][hd])
// ---------------------------------------------------------------------------
#define FL_SMEM_WORDS 34304

__global__ __launch_bounds__(256, 1) void flash_kernel(
    const float* __restrict__ Q, const float* __restrict__ K,
    const float* __restrict__ V, float* __restrict__ O)
{
    extern __shared__ unsigned sm[];
    unsigned* Ks = sm + 16896;
    unsigned* Vs = sm + 25600;

    const int tid  = threadIdx.x;
    const int w    = tid >> 5, lane = tid & 31;
    const int g    = lane >> 2, tg = lane & 3;
    const int bh   = blockIdx.y;
    const int q0   = blockIdx.x * 128;
    const int b    = bh >> 4, h = bh & 15;

    const float* Qp = Q + (size_t)bh * NSEQ * HD;
    const float* Kp = K + (size_t)bh * NSEQ * HD;
    const float* Vp = V + (size_t)bh * NSEQ * HD;

    // ---- stage Q tile -> smem, pick up per-warp A-fragments ----
    #pragma unroll
    for (int i = 0; i < 8; i++) {
        int idx = tid + i * 256;
        int n = idx >> 4, c = (idx & 15) * 4;
        float4 v4 = *(const float4*)(Qp + (size_t)(q0 + n) * HD + c);
        sm[n * 68 + c + 0] = f2tf(v4.x);
        sm[n * 68 + c + 1] = f2tf(v4.y);
        sm[n * 68 + c + 2] = f2tf(v4.z);
        sm[n * 68 + c + 3] = f2tf(v4.w);
    }
    __syncthreads();
    unsigned qf[8][4];
    {
        int qr = w * 16;
        #pragma unroll
        for (int c = 0; c < 8; c++) {
            qf[c][0] = sm[(qr + g)     * 68 + c * 8 + tg];
            qf[c][1] = sm[(qr + g + 8) * 68 + c * 8 + tg];
            qf[c][2] = sm[(qr + g)     * 68 + c * 8 + tg + 4];
            qf[c][3] = sm[(qr + g + 8) * 68 + c * 8 + tg + 4];
        }
    }

    unsigned* Ps = sm + w * 2112;   // 16 rows x 132

    float m0 = -1e30f, m1 = -1e30f, l0 = 0.f, l1 = 0.f;
    float oa[8][4] = {};

    for (int j = 0; j < 16; j++) {
        __syncthreads();   // previous tile fully consumed (also guards Qs->Ps reuse)
        #pragma unroll
        for (int i = 0; i < 8; i++) {
            int idx = tid + i * 256;
            int n = idx >> 4, c = (idx & 15) * 4;
            size_t go = (size_t)(j * 128 + n) * HD + c;
            float4 k4 = *(const float4*)(Kp + go);
            float4 v4 = *(const float4*)(Vp + go);
            Ks[n * 68 + c + 0] = f2tf(k4.x);
            Ks[n * 68 + c + 1] = f2tf(k4.y);
            Ks[n * 68 + c + 2] = f2tf(k4.z);
            Ks[n * 68 + c + 3] = f2tf(k4.w);
            Vs[n * 68 + c + 0] = f2tf(v4.x);
            Vs[n * 68 + c + 1] = f2tf(v4.y);
            Vs[n * 68 + c + 2] = f2tf(v4.z);
            Vs[n * 68 + c + 3] = f2tf(v4.w);
        }
        __syncthreads();

        // ---- S = Q K^T for this warp's 16 rows x 128 kv cols ----
        float s[16][4];
        #pragma unroll
        for (int ni = 0; ni < 16; ni++) {
            s[ni][0] = s[ni][1] = s[ni][2] = s[ni][3] = 0.f;
            #pragma unroll
            for (int ks = 0; ks < 8; ks++) {
                unsigned b0 = Ks[(ni * 8 + g) * 68 + ks * 8 + tg];
                unsigned b1 = Ks[(ni * 8 + g) * 68 + ks * 8 + tg + 4];
                mma8(s[ni], qf[ks][0], qf[ks][1], qf[ks][2], qf[ks][3], b0, b1);
            }
        }

        // ---- online softmax (rows r0 = g, r1 = g+8 of this warp) ----
        float mt0 = -1e30f, mt1 = -1e30f;
        #pragma unroll
        for (int ni = 0; ni < 16; ni++) {
            s[ni][0] *= 0.125f; s[ni][1] *= 0.125f;
            s[ni][2] *= 0.125f; s[ni][3] *= 0.125f;
            mt0 = fmaxf(mt0, fmaxf(s[ni][0], s[ni][1]));
            mt1 = fmaxf(mt1, fmaxf(s[ni][2], s[ni][3]));
        }
        mt0 = fmaxf(mt0, __shfl_xor_sync(~0u, mt0, 1));
        mt0 = fmaxf(mt0, __shfl_xor_sync(~0u, mt0, 2));
        mt1 = fmaxf(mt1, __shfl_xor_sync(~0u, mt1, 1));
        mt1 = fmaxf(mt1, __shfl_xor_sync(~0u, mt1, 2));
        float m0n = fmaxf(m0, mt0), m1n = fmaxf(m1, mt1);
        float c0 = __expf(m0 - m0n), c1 = __expf(m1 - m1n);
        float rs0 = 0.f, rs1 = 0.f;
        #pragma unroll
        for (int ni = 0; ni < 16; ni++) {
            s[ni][0] = __expf(s[ni][0] - m0n);
            s[ni][1] = __expf(s[ni][1] - m0n);
            s[ni][2] = __expf(s[ni][2] - m1n);
            s[ni][3] = __expf(s[ni][3] - m1n);
            rs0 += s[ni][0] + s[ni][1];
            rs1 += s[ni][2] + s[ni][3];
        }
        rs0 += __shfl_xor_sync(~0u, rs0, 1); rs0 += __shfl_xor_sync(~0u, rs0, 2);
        rs1 += __shfl_xor_sync(~0u, rs1, 1); rs1 += __shfl_xor_sync(~0u, rs1, 2);
        l0 = l0 * c0 + rs0; l1 = l1 * c1 + rs1;
        m0 = m0n; m1 = m1n;
        #pragma unroll
        for (int ni = 0; ni < 8; ni++) {
            oa[ni][0] *= c0; oa[ni][1] *= c0;
            oa[ni][2] *= c1; oa[ni][3] *= c1;
        }

        // ---- P -> warp-private smem (C-layout -> A-layout reshape) ----
        __syncwarp();
        #pragma unroll
        for (int ni = 0; ni < 16; ni++) {
            Ps[g * 132       + ni * 8 + 2 * tg]     = f2tf(s[ni][0]);
            Ps[g * 132       + ni * 8 + 2 * tg + 1] = f2tf(s[ni][1]);
            Ps[(g + 8) * 132 + ni * 8 + 2 * tg]     = f2tf(s[ni][2]);
            Ps[(g + 8) * 132 + ni * 8 + 2 * tg + 1] = f2tf(s[ni][3]);
        }
        __syncwarp();

        // ---- O += P V ----
        #pragma unroll
        for (int c = 0; c < 16; c++) {
            unsigned a0 = Ps[g * 132       + c * 8 + tg];
            unsigned a1 = Ps[(g + 8) * 132 + c * 8 + tg];
            unsigned a2 = Ps[g * 132       + c * 8 + tg + 4];
            unsigned a3 = Ps[(g + 8) * 132 + c * 8 + tg + 4];
            #pragma unroll
            for (int ni = 0; ni < 8; ni++) {
                unsigned b0 = Vs[(c * 8 + tg)     * 68 + ni * 8 + g];
                unsigned b1 = Vs[(c * 8 + tg + 4) * 68 + ni * 8 + g];
                mma8(oa[ni], a0, a1, a2, a3, b0, b1);
            }
        }
    }

    // ---- epilogue: O / l -> msgin[b, q, h*64 + hd] ----
    float i0 = 1.f / l0, i1 = 1.f / l1;
    int r0 = q0 + w * 16 + g, r1 = r0 + 8;
    float* Op = O + ((size_t)b * NSEQ) * DIM + h * HD;
    #pragma unroll
    for (int ni = 0; ni < 8; ni++) {
        int cb = ni * 8 + 2 * tg;
        *(float2*)(Op + (size_t)r0 * DIM + cb) =
            make_float2(oa[ni][0] * i0, oa[ni][1] * i0);
        *(float2*)(Op + (size_t)r1 * DIM + cb) =
            make_float2(oa[ni][2] * i1, oa[ni][3] * i1);
    }
}

// ---------------------------------------------------------------------------
// RoPE + QKV split
// ---------------------------------------------------------------------------
__global__ void rope_split_kernel(const float* __restrict__ qkv,
                                  const float* __restrict__ enc)
{
    size_t idx = (size_t)blockIdx.x * blockDim.x + threadIdx.x;
    const size_t total = (size_t)BB * NH * NSEQ * (HD / 2);
    if (idx >= total) return;
    int pair = idx & 31;
    size_t t = idx >> 5;
    int n = t & (NSEQ - 1); t >>= 11;
    int h = t & (NH - 1);
    int b = (int)(t >> 4);

    const float* src = qkv + ((size_t)(b * NSEQ + n) * (3 * DIM)
                              + h * (HD * 3) + pair * 6);
    float q0 = src[0], k0 = src[1], v0 = src[2];
    float q1 = src[3], k1 = src[4], v1 = src[5];

    const float* e0 = enc + (size_t)n * HD + pair * 2;
    const float* e1 = enc + (size_t)NSEQ * HD + (size_t)n * HD + pair * 2;
    float f00 = e0[0], f01 = e0[1], f10 = e1[0], f11 = e1[1];

    size_t o = ((size_t)(b * NH + h) * NSEQ + n) * HD + pair * 2;
    g_q[o]     = q0 * f00 - q1 * f10;
    g_q[o + 1] = q1 * f01 + q0 * f11;
    g_k[o]     = k0 * f00 - k1 * f10;
    g_k[o + 1] = k1 * f01 + k0 * f11;
    g_v[o]     = v0;
    g_v[o + 1] = v1;
}

// LayerNorm (2048) + exact GELU, in place on g_h.
__global__ __launch_bounds__(256) void ln_gelu_kernel(const float* __restrict__ scale,
                                                      const float* __restrict__ bias)
{
    const int n = 2 * DIM;
    float* p = g_h + (size_t)blockIdx.x * n;
    const int tid = threadIdx.x;
    __shared__ float s8a[8], s8b[8];

    float s = 0.f, sq = 0.f;
    for (int i = tid; i < n; i += 256) {
        float v = p[i];
        s += v;
        sq = fmaf(v, v, sq);
    }
    #pragma unroll
    for (int o = 16; o > 0; o >>= 1) {
        s  += __shfl_xor_sync(~0u, s, o);
        sq += __shfl_xor_sync(~0u, sq, o);
    }
    if ((tid & 31) == 0) { s8a[tid >> 5] = s; s8b[tid >> 5] = sq; }
    __syncthreads();
    s = 0.f; sq = 0.f;
    #pragma unroll
    for (int i = 0; i < 8; i++) { s += s8a[i]; sq += s8b[i]; }
    float mu = s / n;
    float var = sq / n - mu * mu;
    float rstd = rsqrtf(var + 1e-5f);

    for (int i = tid; i < n; i += 256) {
        float v = (p[i] - mu) * rstd * scale[i] + bias[i];
        p[i] = 0.5f * v * (1.f + erff(v * 0.70710678118654752f));
    }
}

// ---------------------------------------------------------------------------
// Host
// ---------------------------------------------------------------------------
static inline void* sym(const void* s)
{
    void* p = nullptr;
    cudaGetSymbolAddress(&p, s);
    return p;
}

extern "C" void kernel_launch(void* const* d_in, const int* in_sizes, int n_in,
                              void* d_out, int out_size)
{
    const float* x       = (const float*)d_in[0];
    const float* enc     = (const float*)d_in[1];
    const float* Wqkv_w  = (const float*)d_in[2];
    const float* Wqkv_b  = (const float*)d_in[3];
    const float* out_w   = (const float*)d_in[4];
    const float* out_b   = (const float*)d_in[5];
    const float* ffn0_w  = (const float*)d_in[6];
    const float* ffn0_b  = (const float*)d_in[7];
    const float* ln_s    = (const float*)d_in[8];
    const float* ln_b    = (const float*)d_in[9];
    const float* ffn3_w  = (const float*)d_in[10];
    const float* ffn3_b  = (const float*)d_in[11];
    float* out = (float*)d_out;

    float* qkv   = (float*)sym(g_qkv);
    float* q     = (float*)sym(g_q);
    float* k     = (float*)sym(g_k);
    float* v     = (float*)sym(g_v);
    float* msgin = (float*)sym(g_msgin);
    float* msg   = (float*)sym(g_msg);
    float* hbuf  = (float*)sym(g_h);

    static bool attr_done = false;
    if (!attr_done) {
        cudaFuncSetAttribute(flash_kernel,
            cudaFuncAttributeMaxDynamicSharedMemorySize, FL_SMEM_WORDS * 4);
        attr_done = true;
    }

    // 1. QKV projection
    mma_gemm<128, 2, 4, false><<<dim3(3 * DIM / 128, MTOK / 128, 1), 256>>>(
        x, nullptr, Wqkv_w, Wqkv_b, nullptr, qkv,
        DIM, DIM, DIM, 0, 3 * DIM, 3 * DIM, 0, 0, 0);

    // 2. RoPE + split
    {
        size_t total = (size_t)BB * NH * NSEQ * (HD / 2);
        rope_split_kernel<<<(unsigned)((total + 255) / 256), 256>>>(qkv, enc);
    }

    // 3. Flash attention -> msgin[b,n,h*hd]
    flash_kernel<<<dim3(NSEQ / 128, BHN), 256, FL_SMEM_WORDS * 4>>>(
        q, k, v, msgin);

    // 4. out projection
    mma_gemm<128, 2, 4, false><<<dim3(DIM / 128, MTOK / 128, 1), 256>>>(
        msgin, nullptr, out_w, out_b, nullptr, msg,
        DIM, DIM, DIM, 0, DIM, DIM, 0, 0, 0);

    // 5. FFN0 with fused concat: A = [x | msg]
    mma_gemm<128, 2, 4, false><<<dim3(2 * DIM / 128, MTOK / 128, 1), 256>>>(
        x, msg, ffn0_w, ffn0_b, nullptr, hbuf,
        2 * DIM, DIM, DIM, DIM, 2 * DIM, 2 * DIM, 0, 0, 0);

    // 6. LayerNorm + GELU (in place)
    ln_gelu_kernel<<<MTOK, 256>>>(ln_s, ln_b);

    // 7. FFN3 + residual fused: out = hbuf*W3 + b3 + x
    mma_gemm<128, 2, 4, false><<<dim3(DIM / 128, MTOK / 128, 1), 256>>>(
        hbuf, nullptr, ffn3_w, ffn3_b, x, out,
        2 * DIM, 2 * DIM, 2 * DIM, 0, DIM, DIM, 0, 0, 0);
}

// round 4
// speedup vs baseline: 3.7227x; 1.1847x over previous
#include <cuda_runtime.h>
#include <math.h>

// Problem constants
#define BB    4
#define NSEQ  2048
#define DIM   1024
#define NH    16
#define HD    64
#define MTOK  (BB*NSEQ)      // 8192 tokens
#define BHN   (BB*NH)        // 64 batch*heads

// ---------------------------------------------------------------------------
// Static device scratch
// ---------------------------------------------------------------------------
__device__ float g_xr   [(size_t)MTOK * DIM];        // tf32-rounded x
__device__ float g_qkv  [(size_t)MTOK * 3 * DIM];
__device__ float g_q    [(size_t)BHN * NSEQ * HD];
__device__ float g_k    [(size_t)BHN * NSEQ * HD];
__device__ float g_v    [(size_t)BHN * NSEQ * HD];
__device__ float g_msgin[(size_t)MTOK * DIM];
__device__ float g_msg  [(size_t)MTOK * DIM];
__device__ float g_h    [(size_t)MTOK * 2 * DIM];
// transposed + tf32-rounded weights [N][K]
__device__ float g_wqkvT[(size_t)(3*DIM) * DIM];
__device__ float g_woutT[(size_t)DIM * DIM];
__device__ float g_w0T  [(size_t)(2*DIM) * (2*DIM)];
__device__ float g_w3T  [(size_t)DIM * (2*DIM)];

// ---------------------------------------------------------------------------
// helpers
// ---------------------------------------------------------------------------
__device__ __forceinline__ unsigned f2tf(float f) {
    unsigned r;
    asm("cvt.rna.tf32.f32 %0, %1;" : "=r"(r) : "f"(f));
    return r;
}

__device__ __forceinline__ void mma8(float c[4],
    unsigned a0, unsigned a1, unsigned a2, unsigned a3,
    unsigned b0, unsigned b1)
{
    asm volatile(
        "mma.sync.aligned.m16n8k8.row.col.f32.tf32.tf32.f32 "
        "{%0,%1,%2,%3}, {%4,%5,%6,%7}, {%8,%9}, {%0,%1,%2,%3};"
        : "+f"(c[0]), "+f"(c[1]), "+f"(c[2]), "+f"(c[3])
        : "r"(a0), "r"(a1), "r"(a2), "r"(a3), "r"(b0), "r"(b1));
}

__device__ __forceinline__ void ldsm4(unsigned &r0, unsigned &r1,
                                      unsigned &r2, unsigned &r3, const void* p)
{
    unsigned a = (unsigned)__cvta_generic_to_shared(p);
    asm volatile("ldmatrix.sync.aligned.m8n8.x4.shared.b16 {%0,%1,%2,%3}, [%4];"
                 : "=r"(r0), "=r"(r1), "=r"(r2), "=r"(r3) : "r"(a));
}

__device__ __forceinline__ void cp16(void* s, const void* g)
{
    unsigned a = (unsigned)__cvta_generic_to_shared(s);
    asm volatile("cp.async.cg.shared.global [%0], [%1], 16;" :: "r"(a), "l"(g));
}
#define CP_COMMIT() asm volatile("cp.async.commit_group;")
#define CP_WAIT(n)  asm volatile("cp.async.wait_group %0;" :: "n"(n))

// ---------------------------------------------------------------------------
// tf32 GEMM (all inputs pre-rounded to tf32 bit patterns):
//   C[M,N] = [A | A2][M,K] * BT[N,K]^T (+bias) (+resid)
// BM=BN=128, BK=16, 3-stage cp.async, ldmatrix frags, 2 CTAs/SM.
// Requires: M,N % 128 == 0, K,K1 % 16 == 0.
// smem: 3 stages x (A 128x20 + B 128x20) words = 61440 bytes dynamic.
// ---------------------------------------------------------------------------
template<bool ROUND_C>
__global__ __launch_bounds__(256, 2) void mma_gemm2(
    const float* __restrict__ A, const float* __restrict__ A2,
    const float* __restrict__ BT,
    const float* __restrict__ bias, const float* __restrict__ resid,
    float* __restrict__ C,
    int K, int K1, int lda, int lda2, int ldc)
{
    constexpr int S = 3, BK = 16, LDSW = 20;     // row stride words
    extern __shared__ float smem[];              // stage: A[128][20], B[128][20]

    const int tid  = threadIdx.x;
    const int lane = tid & 31, warp = tid >> 5;
    const int g    = lane >> 2, tg = lane & 3;
    const int wm   = warp & 1, wn = warp >> 1;   // 2 x 4 warp grid, 64x32 tiles
    const int row0 = blockIdx.y * 128, col0 = blockIdx.x * 128;

    // ldmatrix per-thread offsets
    const int lrow = ((lane >> 3) & 1) * 8 + (lane & 7);
    const int lcol = (lane >> 4) * 4;

    float acc[4][4][4] = {};

    auto issue = [&](int kt) {
        int k0 = kt * BK;
        if (k0 < K) {
            float* sa = smem + (kt % S) * 5120;
            float* sb = sa + 2560;
            const float* src = A; int kk = k0, ld = lda;
            if (A2 && k0 >= K1) { src = A2; kk = k0 - K1; ld = lda2; }
            #pragma unroll
            for (int i = 0; i < 2; i++) {
                int idx = tid + i * 256;
                int r = idx >> 2, c = (idx & 3) * 4;
                cp16(sa + r * LDSW + c, src + (size_t)(row0 + r) * ld + kk + c);
                cp16(sb + r * LDSW + c, BT  + (size_t)(col0 + r) * K  + k0 + c);
            }
        }
        CP_COMMIT();
    };

    auto compute = [&](int kt) {
        const float* sa = smem + (kt % S) * 5120;
        const float* sb = sa + 2560;
        #pragma unroll
        for (int ks = 0; ks < 2; ks++) {
            unsigned af[4][4], bf[4][2];
            #pragma unroll
            for (int mi = 0; mi < 4; mi++) {
                ldsm4(af[mi][0], af[mi][1], af[mi][2], af[mi][3],
                      sa + (wm * 64 + mi * 16 + lrow) * LDSW + ks * 8 + lcol);
            }
            #pragma unroll
            for (int p = 0; p < 2; p++) {
                unsigned r0, r1, r2, r3;
                ldsm4(r0, r1, r2, r3,
                      sb + (wn * 32 + p * 16 + lrow) * LDSW + ks * 8 + lcol);
                bf[2*p][0] = r0; bf[2*p+1][0] = r1;
                bf[2*p][1] = r2; bf[2*p+1][1] = r3;
            }
            #pragma unroll
            for (int mi = 0; mi < 4; mi++)
                #pragma unroll
                for (int ni = 0; ni < 4; ni++)
                    mma8(acc[mi][ni], af[mi][0], af[mi][1], af[mi][2], af[mi][3],
                         bf[ni][0], bf[ni][1]);
        }
    };

    issue(0); issue(1);
    const int KT = K / BK;
    CP_WAIT(1); __syncthreads();
    for (int kt = 0; kt < KT; kt++) {
        issue(kt + 2);
        compute(kt);
        CP_WAIT(1); __syncthreads();
    }

    #pragma unroll
    for (int mi = 0; mi < 4; mi++) {
        int rb = row0 + wm * 64 + mi * 16 + g;
        #pragma unroll
        for (int ni = 0; ni < 4; ni++) {
            int cb = col0 + wn * 32 + ni * 8 + 2 * tg;
            float b0v = bias ? bias[cb]     : 0.f;
            float b1v = bias ? bias[cb + 1] : 0.f;
            float v00 = acc[mi][ni][0] + b0v, v01 = acc[mi][ni][1] + b1v;
            float v10 = acc[mi][ni][2] + b0v, v11 = acc[mi][ni][3] + b1v;
            if (resid) {
                v00 += resid[(size_t)rb * ldc + cb];
                v01 += resid[(size_t)rb * ldc + cb + 1];
                v10 += resid[(size_t)(rb + 8) * ldc + cb];
                v11 += resid[(size_t)(rb + 8) * ldc + cb + 1];
            }
            if (ROUND_C) {
                v00 = __uint_as_float(f2tf(v00));
                v01 = __uint_as_float(f2tf(v01));
                v10 = __uint_as_float(f2tf(v10));
                v11 = __uint_as_float(f2tf(v11));
            }
            *(float2*)(C + (size_t)rb * ldc + cb)       = make_float2(v00, v01);
            *(float2*)(C + (size_t)(rb + 8) * ldc + cb) = make_float2(v10, v11);
        }
    }
}

// ---------------------------------------------------------------------------
// Weight prep: out[N][K] = tf32_rna(in[K][N]) transpose
// ---------------------------------------------------------------------------
__global__ void wt_round_T(const float* __restrict__ in, float* __restrict__ out,
                           int K, int N)
{
    __shared__ float t[32][33];
    int n0 = blockIdx.x * 32, k0 = blockIdx.y * 32;
    int tx = threadIdx.x, ty = threadIdx.y;
    #pragma unroll
    for (int i = 0; i < 32; i += 8)
        t[ty + i][tx] = in[(size_t)(k0 + ty + i) * N + n0 + tx];
    __syncthreads();
    #pragma unroll
    for (int i = 0; i < 32; i += 8)
        out[(size_t)(n0 + ty + i) * K + k0 + tx] =
            __uint_as_float(f2tf(t[tx][ty + i]));
}

// x -> tf32-rounded copy
__global__ void x_round_kernel(const float* __restrict__ x)
{
    size_t idx = (size_t)blockIdx.x * blockDim.x + threadIdx.x;
    if (idx >= (size_t)MTOK * DIM) return;
    g_xr[idx] = __uint_as_float(f2tf(x[idx]));
}

// ---------------------------------------------------------------------------
// Flash attention (inputs pre-rounded; raw staging, tf32 mma).
// ---------------------------------------------------------------------------
#define FL_SMEM_WORDS 34304

__global__ __launch_bounds__(256, 1) void flash_kernel(
    const float* __restrict__ Q, const float* __restrict__ K,
    const float* __restrict__ V, float* __restrict__ O)
{
    extern __shared__ unsigned sm[];
    unsigned* Ks = sm + 16896;
    unsigned* Vs = sm + 25600;

    const int tid  = threadIdx.x;
    const int w    = tid >> 5, lane = tid & 31;
    const int g    = lane >> 2, tg = lane & 3;
    const int bh   = blockIdx.y;
    const int q0   = blockIdx.x * 128;
    const int b    = bh >> 4, h = bh & 15;

    const float* Qp = Q + (size_t)bh * NSEQ * HD;
    const float* Kp = K + (size_t)bh * NSEQ * HD;
    const float* Vp = V + (size_t)bh * NSEQ * HD;

    #pragma unroll
    for (int i = 0; i < 8; i++) {
        int idx = tid + i * 256;
        int n = idx >> 4, c = (idx & 15) * 4;
        float4 v4 = *(const float4*)(Qp + (size_t)(q0 + n) * HD + c);
        sm[n * 68 + c + 0] = __float_as_uint(v4.x);
        sm[n * 68 + c + 1] = __float_as_uint(v4.y);
        sm[n * 68 + c + 2] = __float_as_uint(v4.z);
        sm[n * 68 + c + 3] = __float_as_uint(v4.w);
    }
    __syncthreads();
    unsigned qf[8][4];
    {
        int qr = w * 16;
        #pragma unroll
        for (int c = 0; c < 8; c++) {
            qf[c][0] = sm[(qr + g)     * 68 + c * 8 + tg];
            qf[c][1] = sm[(qr + g + 8) * 68 + c * 8 + tg];
            qf[c][2] = sm[(qr + g)     * 68 + c * 8 + tg + 4];
            qf[c][3] = sm[(qr + g + 8) * 68 + c * 8 + tg + 4];
        }
    }

    unsigned* Ps = sm + w * 2112;

    float m0 = -1e30f, m1 = -1e30f, l0 = 0.f, l1 = 0.f;
    float oa[8][4] = {};

    for (int j = 0; j < 16; j++) {
        __syncthreads();
        #pragma unroll
        for (int i = 0; i < 8; i++) {
            int idx = tid + i * 256;
            int n = idx >> 4, c = (idx & 15) * 4;
            size_t go = (size_t)(j * 128 + n) * HD + c;
            float4 k4 = *(const float4*)(Kp + go);
            float4 v4 = *(const float4*)(Vp + go);
            Ks[n * 68 + c + 0] = __float_as_uint(k4.x);
            Ks[n * 68 + c + 1] = __float_as_uint(k4.y);
            Ks[n * 68 + c + 2] = __float_as_uint(k4.z);
            Ks[n * 68 + c + 3] = __float_as_uint(k4.w);
            Vs[n * 68 + c + 0] = __float_as_uint(v4.x);
            Vs[n * 68 + c + 1] = __float_as_uint(v4.y);
            Vs[n * 68 + c + 2] = __float_as_uint(v4.z);
            Vs[n * 68 + c + 3] = __float_as_uint(v4.w);
        }
        __syncthreads();

        float s[16][4];
        #pragma unroll
        for (int ni = 0; ni < 16; ni++) {
            s[ni][0] = s[ni][1] = s[ni][2] = s[ni][3] = 0.f;
            #pragma unroll
            for (int ks = 0; ks < 8; ks++) {
                unsigned b0 = Ks[(ni * 8 + g) * 68 + ks * 8 + tg];
                unsigned b1 = Ks[(ni * 8 + g) * 68 + ks * 8 + tg + 4];
                mma8(s[ni], qf[ks][0], qf[ks][1], qf[ks][2], qf[ks][3], b0, b1);
            }
        }

        float mt0 = -1e30f, mt1 = -1e30f;
        #pragma unroll
        for (int ni = 0; ni < 16; ni++) {
            s[ni][0] *= 0.125f; s[ni][1] *= 0.125f;
            s[ni][2] *= 0.125f; s[ni][3] *= 0.125f;
            mt0 = fmaxf(mt0, fmaxf(s[ni][0], s[ni][1]));
            mt1 = fmaxf(mt1, fmaxf(s[ni][2], s[ni][3]));
        }
        mt0 = fmaxf(mt0, __shfl_xor_sync(~0u, mt0, 1));
        mt0 = fmaxf(mt0, __shfl_xor_sync(~0u, mt0, 2));
        mt1 = fmaxf(mt1, __shfl_xor_sync(~0u, mt1, 1));
        mt1 = fmaxf(mt1, __shfl_xor_sync(~0u, mt1, 2));
        float m0n = fmaxf(m0, mt0), m1n = fmaxf(m1, mt1);
        float c0 = __expf(m0 - m0n), c1 = __expf(m1 - m1n);
        float rs0 = 0.f, rs1 = 0.f;
        #pragma unroll
        for (int ni = 0; ni < 16; ni++) {
            s[ni][0] = __expf(s[ni][0] - m0n);
            s[ni][1] = __expf(s[ni][1] - m0n);
            s[ni][2] = __expf(s[ni][2] - m1n);
            s[ni][3] = __expf(s[ni][3] - m1n);
            rs0 += s[ni][0] + s[ni][1];
            rs1 += s[ni][2] + s[ni][3];
        }
        rs0 += __shfl_xor_sync(~0u, rs0, 1); rs0 += __shfl_xor_sync(~0u, rs0, 2);
        rs1 += __shfl_xor_sync(~0u, rs1, 1); rs1 += __shfl_xor_sync(~0u, rs1, 2);
        l0 = l0 * c0 + rs0; l1 = l1 * c1 + rs1;
        m0 = m0n; m1 = m1n;
        #pragma unroll
        for (int ni = 0; ni < 8; ni++) {
            oa[ni][0] *= c0; oa[ni][1] *= c0;
            oa[ni][2] *= c1; oa[ni][3] *= c1;
        }

        __syncwarp();
        #pragma unroll
        for (int ni = 0; ni < 16; ni++) {
            Ps[g * 132       + ni * 8 + 2 * tg]     = f2tf(s[ni][0]);
            Ps[g * 132       + ni * 8 + 2 * tg + 1] = f2tf(s[ni][1]);
            Ps[(g + 8) * 132 + ni * 8 + 2 * tg]     = f2tf(s[ni][2]);
            Ps[(g + 8) * 132 + ni * 8 + 2 * tg + 1] = f2tf(s[ni][3]);
        }
        __syncwarp();

        #pragma unroll
        for (int c = 0; c < 16; c++) {
            unsigned a0 = Ps[g * 132       + c * 8 + tg];
            unsigned a1 = Ps[(g + 8) * 132 + c * 8 + tg];
            unsigned a2 = Ps[g * 132       + c * 8 + tg + 4];
            unsigned a3 = Ps[(g + 8) * 132 + c * 8 + tg + 4];
            #pragma unroll
            for (int ni = 0; ni < 8; ni++) {
                unsigned b0 = Vs[(c * 8 + tg)     * 68 + ni * 8 + g];
                unsigned b1 = Vs[(c * 8 + tg + 4) * 68 + ni * 8 + g];
                mma8(oa[ni], a0, a1, a2, a3, b0, b1);
            }
        }
    }

    // epilogue: rounded output (feeds out-proj A)
    float i0 = 1.f / l0, i1 = 1.f / l1;
    int r0 = q0 + w * 16 + g, r1 = r0 + 8;
    float* Op = O + ((size_t)b * NSEQ) * DIM + h * HD;
    #pragma unroll
    for (int ni = 0; ni < 8; ni++) {
        int cb = ni * 8 + 2 * tg;
        *(float2*)(Op + (size_t)r0 * DIM + cb) = make_float2(
            __uint_as_float(f2tf(oa[ni][0] * i0)),
            __uint_as_float(f2tf(oa[ni][1] * i0)));
        *(float2*)(Op + (size_t)r1 * DIM + cb) = make_float2(
            __uint_as_float(f2tf(oa[ni][2] * i1)),
            __uint_as_float(f2tf(oa[ni][3] * i1)));
    }
}

// ---------------------------------------------------------------------------
// RoPE + QKV split (writes tf32-rounded q/k/v)
// ---------------------------------------------------------------------------
__global__ void rope_split_kernel(const float* __restrict__ qkv,
                                  const float* __restrict__ enc)
{
    size_t idx = (size_t)blockIdx.x * blockDim.x + threadIdx.x;
    const size_t total = (size_t)BB * NH * NSEQ * (HD / 2);
    if (idx >= total) return;
    int pair = idx & 31;
    size_t t = idx >> 5;
    int n = t & (NSEQ - 1); t >>= 11;
    int h = t & (NH - 1);
    int b = (int)(t >> 4);

    const float* src = qkv + ((size_t)(b * NSEQ + n) * (3 * DIM)
                              + h * (HD * 3) + pair * 6);
    float q0 = src[0], k0 = src[1], v0 = src[2];
    float q1 = src[3], k1 = src[4], v1 = src[5];

    const float* e0 = enc + (size_t)n * HD + pair * 2;
    const float* e1 = enc + (size_t)NSEQ * HD + (size_t)n * HD + pair * 2;
    float f00 = e0[0], f01 = e0[1], f10 = e1[0], f11 = e1[1];

    size_t o = ((size_t)(b * NH + h) * NSEQ + n) * HD + pair * 2;
    g_q[o]     = __uint_as_float(f2tf(q0 * f00 - q1 * f10));
    g_q[o + 1] = __uint_as_float(f2tf(q1 * f01 + q0 * f11));
    g_k[o]     = __uint_as_float(f2tf(k0 * f00 - k1 * f10));
    g_k[o + 1] = __uint_as_float(f2tf(k1 * f01 + k0 * f11));
    g_v[o]     = __uint_as_float(f2tf(v0));
    g_v[o + 1] = __uint_as_float(f2tf(v1));
}

// LayerNorm (2048) + exact GELU, in place, writes tf32-rounded (feeds FFN3 A).
__global__ __launch_bounds__(256) void ln_gelu_kernel(const float* __restrict__ scale,
                                                      const float* __restrict__ bias)
{
    const int n = 2 * DIM;
    float* p = g_h + (size_t)blockIdx.x * n;
    const int tid = threadIdx.x;
    __shared__ float s8a[8], s8b[8];

    float s = 0.f, sq = 0.f;
    for (int i = tid; i < n; i += 256) {
        float v = p[i];
        s += v;
        sq = fmaf(v, v, sq);
    }
    #pragma unroll
    for (int o = 16; o > 0; o >>= 1) {
        s  += __shfl_xor_sync(~0u, s, o);
        sq += __shfl_xor_sync(~0u, sq, o);
    }
    if ((tid & 31) == 0) { s8a[tid >> 5] = s; s8b[tid >> 5] = sq; }
    __syncthreads();
    s = 0.f; sq = 0.f;
    #pragma unroll
    for (int i = 0; i < 8; i++) { s += s8a[i]; sq += s8b[i]; }
    float mu = s / n;
    float var = sq / n - mu * mu;
    float rstd = rsqrtf(var + 1e-5f);

    for (int i = tid; i < n; i += 256) {
        float v = (p[i] - mu) * rstd * scale[i] + bias[i];
        v = 0.5f * v * (1.f + erff(v * 0.70710678118654752f));
        p[i] = __uint_as_float(f2tf(v));
    }
}

// ---------------------------------------------------------------------------
// Host
// ---------------------------------------------------------------------------
static inline void* sym(const void* s)
{
    void* p = nullptr;
    cudaGetSymbolAddress(&p, s);
    return p;
}

#define GEMM_SMEM (3 * 5120 * 4)

extern "C" void kernel_launch(void* const* d_in, const int* in_sizes, int n_in,
                              void* d_out, int out_size)
{
    const float* x       = (const float*)d_in[0];
    const float* enc     = (const float*)d_in[1];
    const float* Wqkv_w  = (const float*)d_in[2];
    const float* Wqkv_b  = (const float*)d_in[3];
    const float* out_w   = (const float*)d_in[4];
    const float* out_b   = (const float*)d_in[5];
    const float* ffn0_w  = (const float*)d_in[6];
    const float* ffn0_b  = (const float*)d_in[7];
    const float* ln_s    = (const float*)d_in[8];
    const float* ln_b    = (const float*)d_in[9];
    const float* ffn3_w  = (const float*)d_in[10];
    const float* ffn3_b  = (const float*)d_in[11];
    float* out = (float*)d_out;

    float* xr    = (float*)sym(g_xr);
    float* qkv   = (float*)sym(g_qkv);
    float* q     = (float*)sym(g_q);
    float* k     = (float*)sym(g_k);
    float* v     = (float*)sym(g_v);
    float* msgin = (float*)sym(g_msgin);
    float* msg   = (float*)sym(g_msg);
    float* hbuf  = (float*)sym(g_h);
    float* wqkvT = (float*)sym(g_wqkvT);
    float* woutT = (float*)sym(g_woutT);
    float* w0T   = (float*)sym(g_w0T);
    float* w3T   = (float*)sym(g_w3T);

    static bool attr_done = false;
    if (!attr_done) {
        cudaFuncSetAttribute(flash_kernel,
            cudaFuncAttributeMaxDynamicSharedMemorySize, FL_SMEM_WORDS * 4);
        cudaFuncSetAttribute(mma_gemm2<false>,
            cudaFuncAttributeMaxDynamicSharedMemorySize, GEMM_SMEM);
        cudaFuncSetAttribute(mma_gemm2<true>,
            cudaFuncAttributeMaxDynamicSharedMemorySize, GEMM_SMEM);
        attr_done = true;
    }

    // 0. prologue: round + transpose weights, round x
    wt_round_T<<<dim3(3 * DIM / 32, DIM / 32), dim3(32, 8)>>>(Wqkv_w, wqkvT, DIM, 3 * DIM);
    wt_round_T<<<dim3(DIM / 32, DIM / 32), dim3(32, 8)>>>(out_w, woutT, DIM, DIM);
    wt_round_T<<<dim3(2 * DIM / 32, 2 * DIM / 32), dim3(32, 8)>>>(ffn0_w, w0T, 2 * DIM, 2 * DIM);
    wt_round_T<<<dim3(DIM / 32, 2 * DIM / 32), dim3(32, 8)>>>(ffn3_w, w3T, 2 * DIM, DIM);
    x_round_kernel<<<(MTOK * DIM + 255) / 256, 256>>>(x);

    // 1. QKV projection
    mma_gemm2<false><<<dim3(3 * DIM / 128, MTOK / 128), 256, GEMM_SMEM>>>(
        xr, nullptr, wqkvT, Wqkv_b, nullptr, qkv, DIM, DIM, DIM, 0, 3 * DIM);

    // 2. RoPE + split (rounded)
    {
        size_t total = (size_t)BB * NH * NSEQ * (HD / 2);
        rope_split_kernel<<<(unsigned)((total + 255) / 256), 256>>>(qkv, enc);
    }

    // 3. Flash attention -> msgin[b,n,h*hd] (rounded)
    flash_kernel<<<dim3(NSEQ / 128, BHN), 256, FL_SMEM_WORDS * 4>>>(
        q, k, v, msgin);

    // 4. out projection (rounded C: feeds FFN0 A)
    mma_gemm2<true><<<dim3(DIM / 128, MTOK / 128), 256, GEMM_SMEM>>>(
        msgin, nullptr, woutT, out_b, nullptr, msg, DIM, DIM, DIM, 0, DIM);

    // 5. FFN0 with fused concat: A = [xr | msg]
    mma_gemm2<false><<<dim3(2 * DIM / 128, MTOK / 128), 256, GEMM_SMEM>>>(
        xr, msg, w0T, ffn0_b, nullptr, hbuf, 2 * DIM, DIM, DIM, DIM, 2 * DIM);

    // 6. LayerNorm + GELU (in place, rounded)
    ln_gelu_kernel<<<MTOK, 256>>>(ln_s, ln_b);

    // 7. FFN3 + residual fused: out = hbuf*W3 + b3 + x
    mma_gemm2<false><<<dim3(DIM / 128, MTOK / 128), 256, GEMM_SMEM>>>(
        hbuf, nullptr, w3T, ffn3_b, x, out, 2 * DIM, 2 * DIM, 2 * DIM, 0, DIM);
}

// round 5
// speedup vs baseline: 4.1543x; 1.1159x over previous
#include <cuda_runtime.h>
#include <math.h>

// Problem constants
#define BB    4
#define NSEQ  2048
#define DIM   1024
#define NH    16
#define HD    64
#define MTOK  (BB*NSEQ)      // 8192 tokens
#define BHN   (BB*NH)        // 64 batch*heads

// ---------------------------------------------------------------------------
// Static device scratch
// ---------------------------------------------------------------------------
__device__ float g_xr   [(size_t)MTOK * DIM];        // tf32-rounded x
__device__ float g_qkv  [(size_t)MTOK * 3 * DIM];
__device__ float g_q    [(size_t)BHN * NSEQ * HD];
__device__ float g_k    [(size_t)BHN * NSEQ * HD];
__device__ float g_v    [(size_t)BHN * NSEQ * HD];
__device__ float g_msgin[(size_t)MTOK * DIM];
__device__ float g_msg  [(size_t)MTOK * DIM];
__device__ float g_h    [(size_t)MTOK * 2 * DIM];
// transposed + tf32-rounded weights [N][K]
__device__ float g_wqkvT[(size_t)(3*DIM) * DIM];
__device__ float g_woutT[(size_t)DIM * DIM];
__device__ float g_w0T  [(size_t)(2*DIM) * (2*DIM)];
__device__ float g_w3T  [(size_t)DIM * (2*DIM)];

// ---------------------------------------------------------------------------
// helpers
// ---------------------------------------------------------------------------
__device__ __forceinline__ unsigned f2tf(float f) {
    unsigned r;
    asm("cvt.rna.tf32.f32 %0, %1;" : "=r"(r) : "f"(f));
    return r;
}

__device__ __forceinline__ void mma8(float c[4],
    unsigned a0, unsigned a1, unsigned a2, unsigned a3,
    unsigned b0, unsigned b1)
{
    asm volatile(
        "mma.sync.aligned.m16n8k8.row.col.f32.tf32.tf32.f32 "
        "{%0,%1,%2,%3}, {%4,%5,%6,%7}, {%8,%9}, {%0,%1,%2,%3};"
        : "+f"(c[0]), "+f"(c[1]), "+f"(c[2]), "+f"(c[3])
        : "r"(a0), "r"(a1), "r"(a2), "r"(a3), "r"(b0), "r"(b1));
}

__device__ __forceinline__ void ldsm4(unsigned &r0, unsigned &r1,
                                      unsigned &r2, unsigned &r3, const void* p)
{
    unsigned a = (unsigned)__cvta_generic_to_shared(p);
    asm volatile("ldmatrix.sync.aligned.m8n8.x4.shared.b16 {%0,%1,%2,%3}, [%4];"
                 : "=r"(r0), "=r"(r1), "=r"(r2), "=r"(r3) : "r"(a));
}

__device__ __forceinline__ void cp16(void* s, const void* g)
{
    unsigned a = (unsigned)__cvta_generic_to_shared(s);
    asm volatile("cp.async.cg.shared.global [%0], [%1], 16;" :: "r"(a), "l"(g));
}
#define CP_COMMIT() asm volatile("cp.async.commit_group;")
#define CP_WAIT(n)  asm volatile("cp.async.wait_group %0;" :: "n"(n))

// ---------------------------------------------------------------------------
// tf32 GEMM (all inputs pre-rounded to tf32 bit patterns):
//   C[M,N] = [A | A2][M,K] * BT[N,K]^T (+bias) (+resid)
// BM=BN=128, BK=32, 3-stage cp.async, ldmatrix frags, 2 CTAs/SM.
// Requires: M,N % 128 == 0, K,K1 % 32 == 0.
// smem: 3 stages x (A[128][36] + B[128][36]) words = 110592 bytes dynamic.
// ---------------------------------------------------------------------------
template<bool ROUND_C>
__global__ __launch_bounds__(256, 2) void mma_gemm2(
    const float* __restrict__ A, const float* __restrict__ A2,
    const float* __restrict__ BT,
    const float* __restrict__ bias, const float* __restrict__ resid,
    float* __restrict__ C,
    int K, int K1, int lda, int lda2, int ldc)
{
    constexpr int S = 3, BK = 32, LDSW = 36;     // row stride words (36%32==4)
    constexpr int STW = 2 * 128 * LDSW;          // words per stage (9216)
    extern __shared__ float smem[];

    const int tid  = threadIdx.x;
    const int lane = tid & 31, warp = tid >> 5;
    const int g    = lane >> 2, tg = lane & 3;
    const int wm   = warp & 1, wn = warp >> 1;   // 2 x 4 warp grid, 64x32 tiles
    const int row0 = blockIdx.y * 128, col0 = blockIdx.x * 128;

    const int lrow = ((lane >> 3) & 1) * 8 + (lane & 7);
    const int lcol = (lane >> 4) * 4;

    float acc[4][4][4] = {};

    auto issue = [&](int kt) {
        int k0 = kt * BK;
        if (k0 < K) {
            float* sa = smem + (kt % S) * STW;
            float* sb = sa + 128 * LDSW;
            const float* src = A; int kk = k0, ld = lda;
            if (A2 && k0 >= K1) { src = A2; kk = k0 - K1; ld = lda2; }
            #pragma unroll
            for (int i = 0; i < 4; i++) {
                int idx = tid + i * 256;        // 1024 f4 = 128 rows x 8
                int r = idx >> 3, c = (idx & 7) * 4;
                cp16(sa + r * LDSW + c, src + (size_t)(row0 + r) * ld + kk + c);
                cp16(sb + r * LDSW + c, BT  + (size_t)(col0 + r) * K  + k0 + c);
            }
        }
        CP_COMMIT();
    };

    auto compute = [&](int kt) {
        const float* sa = smem + (kt % S) * STW;
        const float* sb = sa + 128 * LDSW;
        #pragma unroll
        for (int ks = 0; ks < 4; ks++) {
            unsigned af[4][4], bf[4][2];
            #pragma unroll
            for (int mi = 0; mi < 4; mi++) {
                ldsm4(af[mi][0], af[mi][1], af[mi][2], af[mi][3],
                      sa + (wm * 64 + mi * 16 + lrow) * LDSW + ks * 8 + lcol);
            }
            #pragma unroll
            for (int p = 0; p < 2; p++) {
                unsigned r0, r1, r2, r3;
                ldsm4(r0, r1, r2, r3,
                      sb + (wn * 32 + p * 16 + lrow) * LDSW + ks * 8 + lcol);
                bf[2*p][0] = r0; bf[2*p+1][0] = r1;
                bf[2*p][1] = r2; bf[2*p+1][1] = r3;
            }
            #pragma unroll
            for (int mi = 0; mi < 4; mi++)
                #pragma unroll
                for (int ni = 0; ni < 4; ni++)
                    mma8(acc[mi][ni], af[mi][0], af[mi][1], af[mi][2], af[mi][3],
                         bf[ni][0], bf[ni][1]);
        }
    };

    issue(0); issue(1);
    const int KT = K / BK;
    CP_WAIT(1); __syncthreads();
    for (int kt = 0; kt < KT; kt++) {
        issue(kt + 2);
        compute(kt);
        CP_WAIT(1); __syncthreads();
    }

    #pragma unroll
    for (int mi = 0; mi < 4; mi++) {
        int rb = row0 + wm * 64 + mi * 16 + g;
        #pragma unroll
        for (int ni = 0; ni < 4; ni++) {
            int cb = col0 + wn * 32 + ni * 8 + 2 * tg;
            float b0v = bias ? bias[cb]     : 0.f;
            float b1v = bias ? bias[cb + 1] : 0.f;
            float v00 = acc[mi][ni][0] + b0v, v01 = acc[mi][ni][1] + b1v;
            float v10 = acc[mi][ni][2] + b0v, v11 = acc[mi][ni][3] + b1v;
            if (resid) {
                v00 += resid[(size_t)rb * ldc + cb];
                v01 += resid[(size_t)rb * ldc + cb + 1];
                v10 += resid[(size_t)(rb + 8) * ldc + cb];
                v11 += resid[(size_t)(rb + 8) * ldc + cb + 1];
            }
            if (ROUND_C) {
                v00 = __uint_as_float(f2tf(v00));
                v01 = __uint_as_float(f2tf(v01));
                v10 = __uint_as_float(f2tf(v10));
                v11 = __uint_as_float(f2tf(v11));
            }
            *(float2*)(C + (size_t)rb * ldc + cb)       = make_float2(v00, v01);
            *(float2*)(C + (size_t)(rb + 8) * ldc + cb) = make_float2(v10, v11);
        }
    }
}

// ---------------------------------------------------------------------------
// Weight prep: out[N][K] = tf32_rna(in[K][N]) transpose
// ---------------------------------------------------------------------------
__global__ void wt_round_T(const float* __restrict__ in, float* __restrict__ out,
                           int K, int N)
{
    __shared__ float t[32][33];
    int n0 = blockIdx.x * 32, k0 = blockIdx.y * 32;
    int tx = threadIdx.x, ty = threadIdx.y;
    #pragma unroll
    for (int i = 0; i < 32; i += 8)
        t[ty + i][tx] = in[(size_t)(k0 + ty + i) * N + n0 + tx];
    __syncthreads();
    #pragma unroll
    for (int i = 0; i < 32; i += 8)
        out[(size_t)(n0 + ty + i) * K + k0 + tx] =
            __uint_as_float(f2tf(t[tx][ty + i]));
}

// x -> tf32-rounded copy
__global__ void x_round_kernel(const float* __restrict__ x)
{
    size_t idx = (size_t)blockIdx.x * blockDim.x + threadIdx.x;
    if (idx >= (size_t)MTOK * DIM) return;
    g_xr[idx] = __uint_as_float(f2tf(x[idx]));
}

// ---------------------------------------------------------------------------
// Flash attention (inputs pre-rounded), cp.async double-buffered K/V.
// smem words: [0,16896) Q staging / per-warp Ps; then 2 x (Ks 8704 + Vs 8704).
// total 51712 words = 206848 B.
// ---------------------------------------------------------------------------
#define FL_SMEM_WORDS 51712

__global__ __launch_bounds__(256, 1) void flash_kernel(
    const float* __restrict__ Q, const float* __restrict__ K,
    const float* __restrict__ V, float* __restrict__ O)
{
    extern __shared__ unsigned sm[];

    const int tid  = threadIdx.x;
    const int w    = tid >> 5, lane = tid & 31;
    const int g    = lane >> 2, tg = lane & 3;
    const int bh   = blockIdx.y;
    const int q0   = blockIdx.x * 128;
    const int b    = bh >> 4, h = bh & 15;

    const float* Qp = Q + (size_t)bh * NSEQ * HD;
    const float* Kp = K + (size_t)bh * NSEQ * HD;
    const float* Vp = V + (size_t)bh * NSEQ * HD;

    // thread's staging coords (8 iters x 256 threads covers 128x64)
    const int sn = tid >> 4, sc = (tid & 15) * 4;

    auto issue = [&](int j) {
        unsigned* Kb = sm + 16896 + (j & 1) * 17408;
        unsigned* Vb = Kb + 8704;
        #pragma unroll
        for (int i = 0; i < 8; i++) {
            int n = sn + i * 16;
            size_t go = (size_t)(j * 128 + n) * HD + sc;
            cp16(Kb + n * 68 + sc, Kp + go);
            cp16(Vb + n * 68 + sc, Vp + go);
        }
        CP_COMMIT();
    };

    issue(0);

    // ---- stage Q tile -> smem (plain loads), pick up per-warp A-frags ----
    #pragma unroll
    for (int i = 0; i < 8; i++) {
        int n = sn + i * 16;
        float4 v4 = *(const float4*)(Qp + (size_t)(q0 + n) * HD + sc);
        sm[n * 68 + sc + 0] = __float_as_uint(v4.x);
        sm[n * 68 + sc + 1] = __float_as_uint(v4.y);
        sm[n * 68 + sc + 2] = __float_as_uint(v4.z);
        sm[n * 68 + sc + 3] = __float_as_uint(v4.w);
    }
    __syncthreads();
    unsigned qf[8][4];
    {
        int qr = w * 16;
        #pragma unroll
        for (int c = 0; c < 8; c++) {
            qf[c][0] = sm[(qr + g)     * 68 + c * 8 + tg];
            qf[c][1] = sm[(qr + g + 8) * 68 + c * 8 + tg];
            qf[c][2] = sm[(qr + g)     * 68 + c * 8 + tg + 4];
            qf[c][3] = sm[(qr + g + 8) * 68 + c * 8 + tg + 4];
        }
    }

    unsigned* Ps = sm + w * 2112;

    float m0 = -1e30f, m1 = -1e30f, l0 = 0.f, l1 = 0.f;
    float oa[8][4] = {};

    for (int j = 0; j < 16; j++) {
        if (j < 15) { issue(j + 1); CP_WAIT(1); }
        else        { CP_WAIT(0); }
        __syncthreads();                     // tile j visible to all; qf loaded

        const unsigned* Ks = sm + 16896 + (j & 1) * 17408;
        const unsigned* Vs = Ks + 8704;

        // ---- S = Q K^T ----
        float s[16][4];
        #pragma unroll
        for (int ni = 0; ni < 16; ni++) {
            s[ni][0] = s[ni][1] = s[ni][2] = s[ni][3] = 0.f;
            #pragma unroll
            for (int ks = 0; ks < 8; ks++) {
                unsigned b0 = Ks[(ni * 8 + g) * 68 + ks * 8 + tg];
                unsigned b1 = Ks[(ni * 8 + g) * 68 + ks * 8 + tg + 4];
                mma8(s[ni], qf[ks][0], qf[ks][1], qf[ks][2], qf[ks][3], b0, b1);
            }
        }

        // ---- online softmax ----
        float mt0 = -1e30f, mt1 = -1e30f;
        #pragma unroll
        for (int ni = 0; ni < 16; ni++) {
            s[ni][0] *= 0.125f; s[ni][1] *= 0.125f;
            s[ni][2] *= 0.125f; s[ni][3] *= 0.125f;
            mt0 = fmaxf(mt0, fmaxf(s[ni][0], s[ni][1]));
            mt1 = fmaxf(mt1, fmaxf(s[ni][2], s[ni][3]));
        }
        mt0 = fmaxf(mt0, __shfl_xor_sync(~0u, mt0, 1));
        mt0 = fmaxf(mt0, __shfl_xor_sync(~0u, mt0, 2));
        mt1 = fmaxf(mt1, __shfl_xor_sync(~0u, mt1, 1));
        mt1 = fmaxf(mt1, __shfl_xor_sync(~0u, mt1, 2));
        float m0n = fmaxf(m0, mt0), m1n = fmaxf(m1, mt1);
        float c0 = __expf(m0 - m0n), c1 = __expf(m1 - m1n);
        float rs0 = 0.f, rs1 = 0.f;
        #pragma unroll
        for (int ni = 0; ni < 16; ni++) {
            s[ni][0] = __expf(s[ni][0] - m0n);
            s[ni][1] = __expf(s[ni][1] - m0n);
            s[ni][2] = __expf(s[ni][2] - m1n);
            s[ni][3] = __expf(s[ni][3] - m1n);
            rs0 += s[ni][0] + s[ni][1];
            rs1 += s[ni][2] + s[ni][3];
        }
        rs0 += __shfl_xor_sync(~0u, rs0, 1); rs0 += __shfl_xor_sync(~0u, rs0, 2);
        rs1 += __shfl_xor_sync(~0u, rs1, 1); rs1 += __shfl_xor_sync(~0u, rs1, 2);
        l0 = l0 * c0 + rs0; l1 = l1 * c1 + rs1;
        m0 = m0n; m1 = m1n;
        #pragma unroll
        for (int ni = 0; ni < 8; ni++) {
            oa[ni][0] *= c0; oa[ni][1] *= c0;
            oa[ni][2] *= c1; oa[ni][3] *= c1;
        }

        // ---- P -> warp-private smem (C-layout -> A-layout) ----
        __syncwarp();
        #pragma unroll
        for (int ni = 0; ni < 16; ni++) {
            Ps[g * 132       + ni * 8 + 2 * tg]     = f2tf(s[ni][0]);
            Ps[g * 132       + ni * 8 + 2 * tg + 1] = f2tf(s[ni][1]);
            Ps[(g + 8) * 132 + ni * 8 + 2 * tg]     = f2tf(s[ni][2]);
            Ps[(g + 8) * 132 + ni * 8 + 2 * tg + 1] = f2tf(s[ni][3]);
        }
        __syncwarp();

        // ---- O += P V ----
        #pragma unroll
        for (int c = 0; c < 16; c++) {
            unsigned a0 = Ps[g * 132       + c * 8 + tg];
            unsigned a1 = Ps[(g + 8) * 132 + c * 8 + tg];
            unsigned a2 = Ps[g * 132       + c * 8 + tg + 4];
            unsigned a3 = Ps[(g + 8) * 132 + c * 8 + tg + 4];
            #pragma unroll
            for (int ni = 0; ni < 8; ni++) {
                unsigned b0 = Vs[(c * 8 + tg)     * 68 + ni * 8 + g];
                unsigned b1 = Vs[(c * 8 + tg + 4) * 68 + ni * 8 + g];
                mma8(oa[ni], a0, a1, a2, a3, b0, b1);
            }
        }
        __syncthreads();  // all threads done with buffer (j&1) before overwrite
    }

    // epilogue: rounded output (feeds out-proj A)
    float i0 = 1.f / l0, i1 = 1.f / l1;
    int r0 = q0 + w * 16 + g, r1 = r0 + 8;
    float* Op = O + ((size_t)b * NSEQ) * DIM + h * HD;
    #pragma unroll
    for (int ni = 0; ni < 8; ni++) {
        int cb = ni * 8 + 2 * tg;
        *(float2*)(Op + (size_t)r0 * DIM + cb) = make_float2(
            __uint_as_float(f2tf(oa[ni][0] * i0)),
            __uint_as_float(f2tf(oa[ni][1] * i0)));
        *(float2*)(Op + (size_t)r1 * DIM + cb) = make_float2(
            __uint_as_float(f2tf(oa[ni][2] * i1)),
            __uint_as_float(f2tf(oa[ni][3] * i1)));
    }
}

// ---------------------------------------------------------------------------
// RoPE + QKV split (writes tf32-rounded q/k/v)
// ---------------------------------------------------------------------------
__global__ void rope_split_kernel(const float* __restrict__ qkv,
                                  const float* __restrict__ enc)
{
    size_t idx = (size_t)blockIdx.x * blockDim.x + threadIdx.x;
    const size_t total = (size_t)BB * NH * NSEQ * (HD / 2);
    if (idx >= total) return;
    int pair = idx & 31;
    size_t t = idx >> 5;
    int n = t & (NSEQ - 1); t >>= 11;
    int h = t & (NH - 1);
    int b = (int)(t >> 4);

    const float* src = qkv + ((size_t)(b * NSEQ + n) * (3 * DIM)
                              + h * (HD * 3) + pair * 6);
    float q0 = src[0], k0 = src[1], v0 = src[2];
    float q1 = src[3], k1 = src[4], v1 = src[5];

    const float* e0 = enc + (size_t)n * HD + pair * 2;
    const float* e1 = enc + (size_t)NSEQ * HD + (size_t)n * HD + pair * 2;
    float f00 = e0[0], f01 = e0[1], f10 = e1[0], f11 = e1[1];

    size_t o = ((size_t)(b * NH + h) * NSEQ + n) * HD + pair * 2;
    g_q[o]     = __uint_as_float(f2tf(q0 * f00 - q1 * f10));
    g_q[o + 1] = __uint_as_float(f2tf(q1 * f01 + q0 * f11));
    g_k[o]     = __uint_as_float(f2tf(k0 * f00 - k1 * f10));
    g_k[o + 1] = __uint_as_float(f2tf(k1 * f01 + k0 * f11));
    g_v[o]     = __uint_as_float(f2tf(v0));
    g_v[o + 1] = __uint_as_float(f2tf(v1));
}

// LayerNorm (2048) + exact GELU, in place, writes tf32-rounded (feeds FFN3 A).
__global__ __launch_bounds__(256) void ln_gelu_kernel(const float* __restrict__ scale,
                                                      const float* __restrict__ bias)
{
    const int n = 2 * DIM;
    float* p = g_h + (size_t)blockIdx.x * n;
    const int tid = threadIdx.x;
    __shared__ float s8a[8], s8b[8];

    float s = 0.f, sq = 0.f;
    for (int i = tid; i < n; i += 256) {
        float v = p[i];
        s += v;
        sq = fmaf(v, v, sq);
    }
    #pragma unroll
    for (int o = 16; o > 0; o >>= 1) {
        s  += __shfl_xor_sync(~0u, s, o);
        sq += __shfl_xor_sync(~0u, sq, o);
    }
    if ((tid & 31) == 0) { s8a[tid >> 5] = s; s8b[tid >> 5] = sq; }
    __syncthreads();
    s = 0.f; sq = 0.f;
    #pragma unroll
    for (int i = 0; i < 8; i++) { s += s8a[i]; sq += s8b[i]; }
    float mu = s / n;
    float var = sq / n - mu * mu;
    float rstd = rsqrtf(var + 1e-5f);

    for (int i = tid; i < n; i += 256) {
        float v = (p[i] - mu) * rstd * scale[i] + bias[i];
        v = 0.5f * v * (1.f + erff(v * 0.70710678118654752f));
        p[i] = __uint_as_float(f2tf(v));
    }
}

// ---------------------------------------------------------------------------
// Host
// ---------------------------------------------------------------------------
static inline void* sym(const void* s)
{
    void* p = nullptr;
    cudaGetSymbolAddress(&p, s);
    return p;
}

#define GEMM_SMEM (3 * 9216 * 4)

extern "C" void kernel_launch(void* const* d_in, const int* in_sizes, int n_in,
                              void* d_out, int out_size)
{
    const float* x       = (const float*)d_in[0];
    const float* enc     = (const float*)d_in[1];
    const float* Wqkv_w  = (const float*)d_in[2];
    const float* Wqkv_b  = (const float*)d_in[3];
    const float* out_w   = (const float*)d_in[4];
    const float* out_b   = (const float*)d_in[5];
    const float* ffn0_w  = (const float*)d_in[6];
    const float* ffn0_b  = (const float*)d_in[7];
    const float* ln_s    = (const float*)d_in[8];
    const float* ln_b    = (const float*)d_in[9];
    const float* ffn3_w  = (const float*)d_in[10];
    const float* ffn3_b  = (const float*)d_in[11];
    float* out = (float*)d_out;

    float* xr    = (float*)sym(g_xr);
    float* qkv   = (float*)sym(g_qkv);
    float* q     = (float*)sym(g_q);
    float* k     = (float*)sym(g_k);
    float* v     = (float*)sym(g_v);
    float* msgin = (float*)sym(g_msgin);
    float* msg   = (float*)sym(g_msg);
    float* hbuf  = (float*)sym(g_h);
    float* wqkvT = (float*)sym(g_wqkvT);
    float* woutT = (float*)sym(g_woutT);
    float* w0T   = (float*)sym(g_w0T);
    float* w3T   = (float*)sym(g_w3T);

    static bool attr_done = false;
    if (!attr_done) {
        cudaFuncSetAttribute(flash_kernel,
            cudaFuncAttributeMaxDynamicSharedMemorySize, FL_SMEM_WORDS * 4);
        cudaFuncSetAttribute(mma_gemm2<false>,
            cudaFuncAttributeMaxDynamicSharedMemorySize, GEMM_SMEM);
        cudaFuncSetAttribute(mma_gemm2<true>,
            cudaFuncAttributeMaxDynamicSharedMemorySize, GEMM_SMEM);
        attr_done = true;
    }

    // 0. prologue: round + transpose weights, round x
    wt_round_T<<<dim3(3 * DIM / 32, DIM / 32), dim3(32, 8)>>>(Wqkv_w, wqkvT, DIM, 3 * DIM);
    wt_round_T<<<dim3(DIM / 32, DIM / 32), dim3(32, 8)>>>(out_w, woutT, DIM, DIM);
    wt_round_T<<<dim3(2 * DIM / 32, 2 * DIM / 32), dim3(32, 8)>>>(ffn0_w, w0T, 2 * DIM, 2 * DIM);
    wt_round_T<<<dim3(DIM / 32, 2 * DIM / 32), dim3(32, 8)>>>(ffn3_w, w3T, 2 * DIM, DIM);
    x_round_kernel<<<(MTOK * DIM + 255) / 256, 256>>>(x);

    // 1. QKV projection
    mma_gemm2<false><<<dim3(3 * DIM / 128, MTOK / 128), 256, GEMM_SMEM>>>(
        xr, nullptr, wqkvT, Wqkv_b, nullptr, qkv, DIM, DIM, DIM, 0, 3 * DIM);

    // 2. RoPE + split (rounded)
    {
        size_t total = (size_t)BB * NH * NSEQ * (HD / 2);
        rope_split_kernel<<<(unsigned)((total + 255) / 256), 256>>>(qkv, enc);
    }

    // 3. Flash attention -> msgin[b,n,h*hd] (rounded)
    flash_kernel<<<dim3(NSEQ / 128, BHN), 256, FL_SMEM_WORDS * 4>>>(
        q, k, v, msgin);

    // 4. out projection (rounded C: feeds FFN0 A)
    mma_gemm2<true><<<dim3(DIM / 128, MTOK / 128), 256, GEMM_SMEM>>>(
        msgin, nullptr, woutT, out_b, nullptr, msg, DIM, DIM, DIM, 0, DIM);

    // 5. FFN0 with fused concat: A = [xr | msg]
    mma_gemm2<false><<<dim3(2 * DIM / 128, MTOK / 128), 256, GEMM_SMEM>>>(
        xr, msg, w0T, ffn0_b, nullptr, hbuf, 2 * DIM, DIM, DIM, DIM, 2 * DIM);

    // 6. LayerNorm + GELU (in place, rounded)
    ln_gelu_kernel<<<MTOK, 256>>>(ln_s, ln_b);

    // 7. FFN3 + residual fused: out = hbuf*W3 + b3 + x
    mma_gemm2<false><<<dim3(DIM / 128, MTOK / 128), 256, GEMM_SMEM>>>(
        hbuf, nullptr, w3T, ffn3_b, x, out, 2 * DIM, 2 * DIM, 2 * DIM, 0, DIM);
}

// round 8
// speedup vs baseline: 8.7920x; 2.1164x over previous
#include <cuda_runtime.h>
#include <cuda_fp16.h>
#include <math.h>
#include <stdint.h>

// Problem constants
#define BB    4
#define NSEQ  2048
#define DIM   1024
#define NH    16
#define HD    64
#define MTOK  (BB*NSEQ)      // 8192 tokens
#define BHN   (BB*NH)        // 64 batch*heads

// ---------------------------------------------------------------------------
// Static device scratch (fp16 activations/weights)
// ---------------------------------------------------------------------------
__device__ __half g_xr   [(size_t)MTOK * DIM];
__device__ __half g_qkv  [(size_t)MTOK * 3 * DIM];
__device__ __half g_q    [(size_t)BHN * NSEQ * HD];
__device__ __half g_k    [(size_t)BHN * NSEQ * HD];
__device__ __half g_v    [(size_t)BHN * NSEQ * HD];
__device__ __half g_msgin[(size_t)MTOK * DIM];
__device__ __half g_msg  [(size_t)MTOK * DIM];
__device__ __half g_h    [(size_t)MTOK * 2 * DIM];
// transposed + fp16-rounded weights [N][K]
__device__ __half g_wqkvT[(size_t)(3*DIM) * DIM];
__device__ __half g_woutT[(size_t)DIM * DIM];
__device__ __half g_w0T  [(size_t)(2*DIM) * (2*DIM)];
__device__ __half g_w3T  [(size_t)DIM * (2*DIM)];

// ---------------------------------------------------------------------------
// helpers
// ---------------------------------------------------------------------------
__device__ __forceinline__ void mma16(float c[4], const unsigned a[4],
                                      unsigned b0, unsigned b1)
{
    asm volatile(
        "mma.sync.aligned.m16n8k16.row.col.f32.f16.f16.f32 "
        "{%0,%1,%2,%3}, {%4,%5,%6,%7}, {%8,%9}, {%0,%1,%2,%3};"
        : "+f"(c[0]), "+f"(c[1]), "+f"(c[2]), "+f"(c[3])
        : "r"(a[0]), "r"(a[1]), "r"(a[2]), "r"(a[3]), "r"(b0), "r"(b1));
}

__device__ __forceinline__ void ldsm4(unsigned &r0, unsigned &r1,
                                      unsigned &r2, unsigned &r3, const void* p)
{
    unsigned a = (unsigned)__cvta_generic_to_shared(p);
    asm volatile("ldmatrix.sync.aligned.m8n8.x4.shared.b16 {%0,%1,%2,%3}, [%4];"
                 : "=r"(r0), "=r"(r1), "=r"(r2), "=r"(r3) : "r"(a));
}

__device__ __forceinline__ void ldsm4t(unsigned &r0, unsigned &r1,
                                       unsigned &r2, unsigned &r3, const void* p)
{
    unsigned a = (unsigned)__cvta_generic_to_shared(p);
    asm volatile("ldmatrix.sync.aligned.m8n8.x4.trans.shared.b16 {%0,%1,%2,%3}, [%4];"
                 : "=r"(r0), "=r"(r1), "=r"(r2), "=r"(r3) : "r"(a));
}

__device__ __forceinline__ void cp16(void* s, const void* g)
{
    unsigned a = (unsigned)__cvta_generic_to_shared(s);
    asm volatile("cp.async.cg.shared.global [%0], [%1], 16;" :: "r"(a), "l"(g));
}
#define CP_COMMIT() asm volatile("cp.async.commit_group;")
#define CP_WAIT(n)  asm volatile("cp.async.wait_group %0;" :: "n"(n))

// ---------------------------------------------------------------------------
// fp16 GEMM: C[M,N] = [A | A2][M,K] * BT[N,K]^T + bias (+resid)
// BM=BN=128, BK=64 halves, 3-stage cp.async, ldmatrix x4 frags, 2 CTAs/SM.
// ---------------------------------------------------------------------------
#define GS_LDH   72
#define GS_STAGE (2 * 128 * GS_LDH)          // halves per stage
#define GEMM_SMEM (3 * GS_STAGE * 2)         // bytes

template<int OUT_HALF>
__global__ __launch_bounds__(256, 2) void hgemm(
    const __half* __restrict__ A, const __half* __restrict__ A2,
    const __half* __restrict__ BT,
    const float* __restrict__ bias, const float* __restrict__ resid,
    void* __restrict__ Cv,
    int K, int K1, int lda, int lda2, int ldc)
{
    extern __shared__ __half hs[];
    const int tid  = threadIdx.x;
    const int lane = tid & 31, warp = tid >> 5;
    const int g    = lane >> 2, tg = lane & 3;
    const int wm   = warp & 1, wn = warp >> 1;       // 2x4 warps, 64x32 tiles
    const int row0 = blockIdx.y * 128, col0 = blockIdx.x * 128;

    const int lrow = (lane & 7) + ((lane >> 3) & 1) * 8;   // A ldsm row
    const int lcol = ((lane >> 4) & 1) * 8;                // A ldsm col (halves)
    const int brow = (lane & 7) + ((lane >> 4) & 1) * 8;   // B ldsm row
    const int bcol = ((lane >> 3) & 1) * 8;                // B ldsm col

    float acc[4][4][4] = {};

    auto issue = [&](int kt) {
        int k0 = kt * 64;
        if (k0 < K) {
            __half* sa = hs + (kt % 3) * GS_STAGE;
            __half* sb = sa + 128 * GS_LDH;
            const __half* Asrc = A; int kk = k0, ld = lda;
            if (A2 && k0 >= K1) { Asrc = A2; kk = k0 - K1; ld = lda2; }
            #pragma unroll
            for (int i = 0; i < 4; i++) {
                int id = tid + i * 256;
                int r = id >> 3, c = (id & 7) * 8;
                cp16(sa + r * GS_LDH + c, Asrc + (size_t)(row0 + r) * ld + kk + c);
                cp16(sb + r * GS_LDH + c, BT + (size_t)(col0 + r) * K + k0 + c);
            }
        }
        CP_COMMIT();
    };

    auto compute = [&](int kt) {
        const __half* sa = hs + (kt % 3) * GS_STAGE;
        const __half* sb = sa + 128 * GS_LDH;
        #pragma unroll
        for (int ks = 0; ks < 4; ks++) {
            unsigned af[4][4], bf[4][2];
            #pragma unroll
            for (int mi = 0; mi < 4; mi++)
                ldsm4(af[mi][0], af[mi][1], af[mi][2], af[mi][3],
                      sa + (wm * 64 + mi * 16 + lrow) * GS_LDH + ks * 16 + lcol);
            #pragma unroll
            for (int p = 0; p < 2; p++) {
                unsigned r0, r1, r2, r3;
                ldsm4(r0, r1, r2, r3,
                      sb + (wn * 32 + p * 16 + brow) * GS_LDH + ks * 16 + bcol);
                bf[2*p][0] = r0; bf[2*p][1] = r1;
                bf[2*p+1][0] = r2; bf[2*p+1][1] = r3;
            }
            #pragma unroll
            for (int mi = 0; mi < 4; mi++)
                #pragma unroll
                for (int ni = 0; ni < 4; ni++)
                    mma16(acc[mi][ni], af[mi], bf[ni][0], bf[ni][1]);
        }
    };

    issue(0); issue(1);
    const int KT = K / 64;
    CP_WAIT(1); __syncthreads();
    for (int kt = 0; kt < KT; kt++) {
        issue(kt + 2);
        compute(kt);
        CP_WAIT(1); __syncthreads();
    }

    #pragma unroll
    for (int mi = 0; mi < 4; mi++) {
        int rb = row0 + wm * 64 + mi * 16 + g;
        #pragma unroll
        for (int ni = 0; ni < 4; ni++) {
            int cb = col0 + wn * 32 + ni * 8 + 2 * tg;
            float b0v = bias[cb], b1v = bias[cb + 1];
            float v00 = acc[mi][ni][0] + b0v, v01 = acc[mi][ni][1] + b1v;
            float v10 = acc[mi][ni][2] + b0v, v11 = acc[mi][ni][3] + b1v;
            if (OUT_HALF) {
                __half* C = (__half*)Cv;
                *(__half2*)(C + (size_t)rb * ldc + cb) = __floats2half2_rn(v00, v01);
                *(__half2*)(C + (size_t)(rb + 8) * ldc + cb) = __floats2half2_rn(v10, v11);
            } else {
                float* C = (float*)Cv;
                v00 += resid[(size_t)rb * ldc + cb];
                v01 += resid[(size_t)rb * ldc + cb + 1];
                v10 += resid[(size_t)(rb + 8) * ldc + cb];
                v11 += resid[(size_t)(rb + 8) * ldc + cb + 1];
                *(float2*)(C + (size_t)rb * ldc + cb)       = make_float2(v00, v01);
                *(float2*)(C + (size_t)(rb + 8) * ldc + cb) = make_float2(v10, v11);
            }
        }
    }
}

// ---------------------------------------------------------------------------
// Weight prep: out[N][K] = fp16(in[K][N]) transpose
// ---------------------------------------------------------------------------
__global__ void wt_round_T(const float* __restrict__ in, __half* __restrict__ out,
                           int K, int N)
{
    __shared__ float t[32][33];
    int n0 = blockIdx.x * 32, k0 = blockIdx.y * 32;
    int tx = threadIdx.x, ty = threadIdx.y;
    #pragma unroll
    for (int i = 0; i < 32; i += 8)
        t[ty + i][tx] = in[(size_t)(k0 + ty + i) * N + n0 + tx];
    __syncthreads();
    #pragma unroll
    for (int i = 0; i < 32; i += 8)
        out[(size_t)(n0 + ty + i) * K + k0 + tx] = __float2half_rn(t[tx][ty + i]);
}

// x -> fp16 copy
__global__ void x_round_kernel(const float* __restrict__ x)
{
    size_t idx = (size_t)blockIdx.x * blockDim.x + threadIdx.x;
    if (idx >= (size_t)MTOK * DIM / 2) return;
    float2 v = *(const float2*)(x + idx * 2);
    *(__half2*)(g_xr + idx * 2) = __floats2half2_rn(v.x, v.y);
}

// ---------------------------------------------------------------------------
// Flash attention, fp16 mma m16n8k16, HD=64, cp.async double-buffered K/V.
// smem layout (halves):
//   [0, 9216)        Qs [128][72]           (Q staging; frags consumed early)
//   [9216, 26624)    Ps: per-warp 16 x 136  (8 warps x 2176)
//   [26624, 63488)   2 x (Ks [128][72] + Vs [128][72])
// Total 63488 halves = 126976 B.
// ---------------------------------------------------------------------------
#define FL_PS_OFF   9216
#define FL_PS_LDH   136          // 68 words == 4 mod 32 -> conflict-free
#define FL_KV_OFF   26624
#define FL_SMEM_BYTES (63488 * 2)

__global__ __launch_bounds__(256, 1) void flash_kernel(
    const __half* __restrict__ Q, const __half* __restrict__ K,
    const __half* __restrict__ V, __half* __restrict__ O)
{
    extern __shared__ __half sm[];

    const int tid  = threadIdx.x;
    const int w    = tid >> 5, lane = tid & 31;
    const int g    = lane >> 2, tg = lane & 3;
    const int bh   = blockIdx.y;
    const int q0   = blockIdx.x * 128;
    const int b    = bh >> 4, h = bh & 15;

    const int lrow = (lane & 7) + ((lane >> 3) & 1) * 8;
    const int lcol = ((lane >> 4) & 1) * 8;
    const int brow = (lane & 7) + ((lane >> 4) & 1) * 8;
    const int bcol = ((lane >> 3) & 1) * 8;

    const __half* Qp = Q + (size_t)bh * NSEQ * HD;
    const __half* Kp = K + (size_t)bh * NSEQ * HD;
    const __half* Vp = V + (size_t)bh * NSEQ * HD;

    auto issue = [&](int j) {
        __half* Kb = sm + FL_KV_OFF + (j & 1) * 18432;
        __half* Vb = Kb + 9216;
        #pragma unroll
        for (int i = 0; i < 4; i++) {
            int id = tid + i * 256;
            int r = id >> 3, c = (id & 7) * 8;
            size_t go = (size_t)(j * 128 + r) * HD + c;
            cp16(Kb + r * 72 + c, Kp + go);
            cp16(Vb + r * 72 + c, Vp + go);
        }
        CP_COMMIT();
    };

    issue(0);

    // ---- stage Q tile (plain loads), extract per-warp A-frags ----
    #pragma unroll
    for (int i = 0; i < 4; i++) {
        int id = tid + i * 256;
        int r = id >> 3, c = (id & 7) * 8;
        *(uint4*)(sm + r * 72 + c) = *(const uint4*)(Qp + (size_t)(q0 + r) * HD + c);
    }
    __syncthreads();
    unsigned qf[4][4];
    #pragma unroll
    for (int ks = 0; ks < 4; ks++)
        ldsm4(qf[ks][0], qf[ks][1], qf[ks][2], qf[ks][3],
              sm + (w * 16 + lrow) * 72 + ks * 16 + lcol);

    __half* Ps = sm + FL_PS_OFF + w * (16 * FL_PS_LDH);

    float m0 = -1e30f, m1 = -1e30f, l0 = 0.f, l1 = 0.f;
    float oa[8][4] = {};

    for (int j = 0; j < 16; j++) {
        if (j < 15) { issue(j + 1); CP_WAIT(1); }
        else        { CP_WAIT(0); }
        __syncthreads();

        const __half* Ks = sm + FL_KV_OFF + (j & 1) * 18432;
        const __half* Vs = Ks + 9216;

        // ---- S = Q K^T (16 q rows x 128 kv per warp) ----
        float s[16][4];
        #pragma unroll
        for (int ni = 0; ni < 16; ni++)
            s[ni][0] = s[ni][1] = s[ni][2] = s[ni][3] = 0.f;
        #pragma unroll
        for (int ks = 0; ks < 4; ks++) {
            #pragma unroll
            for (int n2 = 0; n2 < 8; n2++) {
                unsigned r0, r1, r2, r3;
                ldsm4(r0, r1, r2, r3,
                      Ks + (n2 * 16 + brow) * 72 + ks * 16 + bcol);
                mma16(s[2*n2],     qf[ks], r0, r1);
                mma16(s[2*n2 + 1], qf[ks], r2, r3);
            }
        }

        // ---- online softmax ----
        float mt0 = -1e30f, mt1 = -1e30f;
        #pragma unroll
        for (int ni = 0; ni < 16; ni++) {
            s[ni][0] *= 0.125f; s[ni][1] *= 0.125f;
            s[ni][2] *= 0.125f; s[ni][3] *= 0.125f;
            mt0 = fmaxf(mt0, fmaxf(s[ni][0], s[ni][1]));
            mt1 = fmaxf(mt1, fmaxf(s[ni][2], s[ni][3]));
        }
        mt0 = fmaxf(mt0, __shfl_xor_sync(~0u, mt0, 1));
        mt0 = fmaxf(mt0, __shfl_xor_sync(~0u, mt0, 2));
        mt1 = fmaxf(mt1, __shfl_xor_sync(~0u, mt1, 1));
        mt1 = fmaxf(mt1, __shfl_xor_sync(~0u, mt1, 2));
        float m0n = fmaxf(m0, mt0), m1n = fmaxf(m1, mt1);
        float c0 = __expf(m0 - m0n), c1 = __expf(m1 - m1n);
        float rs0 = 0.f, rs1 = 0.f;
        #pragma unroll
        for (int ni = 0; ni < 16; ni++) {
            s[ni][0] = __expf(s[ni][0] - m0n);
            s[ni][1] = __expf(s[ni][1] - m0n);
            s[ni][2] = __expf(s[ni][2] - m1n);
            s[ni][3] = __expf(s[ni][3] - m1n);
            rs0 += s[ni][0] + s[ni][1];
            rs1 += s[ni][2] + s[ni][3];
        }
        rs0 += __shfl_xor_sync(~0u, rs0, 1); rs0 += __shfl_xor_sync(~0u, rs0, 2);
        rs1 += __shfl_xor_sync(~0u, rs1, 1); rs1 += __shfl_xor_sync(~0u, rs1, 2);
        l0 = l0 * c0 + rs0; l1 = l1 * c1 + rs1;
        m0 = m0n; m1 = m1n;
        #pragma unroll
        for (int ni = 0; ni < 8; ni++) {
            oa[ni][0] *= c0; oa[ni][1] *= c0;
            oa[ni][2] *= c1; oa[ni][3] *= c1;
        }

        // ---- P -> warp-private smem (C-layout -> A-layout) ----
        __syncwarp();
        {
            __half2* p0 = (__half2*)(Ps + (size_t)g * FL_PS_LDH);
            __half2* p1 = (__half2*)(Ps + (size_t)(g + 8) * FL_PS_LDH);
            #pragma unroll
            for (int ni = 0; ni < 16; ni++) {
                p0[ni * 4 + tg] = __floats2half2_rn(s[ni][0], s[ni][1]);
                p1[ni * 4 + tg] = __floats2half2_rn(s[ni][2], s[ni][3]);
            }
        }
        __syncwarp();

        // ---- O += P V ----
        #pragma unroll
        for (int c = 0; c < 8; c++) {
            unsigned a[4];
            ldsm4(a[0], a[1], a[2], a[3],
                  Ps + (size_t)lrow * FL_PS_LDH + c * 16 + lcol);
            #pragma unroll
            for (int n2 = 0; n2 < 4; n2++) {
                unsigned r0, r1, r2, r3;
                ldsm4t(r0, r1, r2, r3,
                       Vs + (c * 16 + lrow) * 72 + n2 * 16 + lcol);
                mma16(oa[2*n2],     a, r0, r1);
                mma16(oa[2*n2 + 1], a, r2, r3);
            }
        }
        __syncthreads();
    }

    // ---- epilogue: O / l -> msgin[b, q, h*64+hd] (fp16) ----
    float i0 = 1.f / l0, i1 = 1.f / l1;
    int r0 = q0 + w * 16 + g, r1 = r0 + 8;
    __half* Op = O + ((size_t)b * NSEQ) * DIM + h * HD;
    #pragma unroll
    for (int ni = 0; ni < 8; ni++) {
        int cb = ni * 8 + 2 * tg;
        *(__half2*)(Op + (size_t)r0 * DIM + cb) =
            __floats2half2_rn(oa[ni][0] * i0, oa[ni][1] * i0);
        *(__half2*)(Op + (size_t)r1 * DIM + cb) =
            __floats2half2_rn(oa[ni][2] * i1, oa[ni][3] * i1);
    }
}

// ---------------------------------------------------------------------------
// RoPE + QKV split (half in, half out)
// ---------------------------------------------------------------------------
__global__ void rope_split_kernel(const __half* __restrict__ qkv,
                                  const float* __restrict__ enc)
{
    size_t idx = (size_t)blockIdx.x * blockDim.x + threadIdx.x;
    const size_t total = (size_t)BB * NH * NSEQ * (HD / 2);
    if (idx >= total) return;
    int pair = idx & 31;
    size_t t = idx >> 5;
    int n = t & (NSEQ - 1); t >>= 11;
    int h = t & (NH - 1);
    int b = (int)(t >> 4);

    const __half* src = qkv + ((size_t)(b * NSEQ + n) * (3 * DIM)
                               + h * (HD * 3) + pair * 6);
    float q0 = __half2float(src[0]), k0 = __half2float(src[1]);
    float v0 = __half2float(src[2]), q1 = __half2float(src[3]);
    float k1 = __half2float(src[4]), v1 = __half2float(src[5]);

    const float* e0 = enc + (size_t)n * HD + pair * 2;
    const float* e1 = enc + (size_t)NSEQ * HD + (size_t)n * HD + pair * 2;
    float f00 = e0[0], f01 = e0[1], f10 = e1[0], f11 = e1[1];

    size_t o = ((size_t)(b * NH + h) * NSEQ + n) * HD + pair * 2;
    *(__half2*)(g_q + o) = __floats2half2_rn(q0 * f00 - q1 * f10,
                                             q1 * f01 + q0 * f11);
    *(__half2*)(g_k + o) = __floats2half2_rn(k0 * f00 - k1 * f10,
                                             k1 * f01 + k0 * f11);
    *(__half2*)(g_v + o) = __floats2half2_rn(v0, v1);
}

// LayerNorm (2048) + exact GELU, in place on g_h (half).
__global__ __launch_bounds__(256) void ln_gelu_kernel(const float* __restrict__ scale,
                                                      const float* __restrict__ bias)
{
    const int n = 2 * DIM;
    __half* p = g_h + (size_t)blockIdx.x * n;
    const int tid = threadIdx.x;
    __shared__ float s8a[8], s8b[8];

    float s = 0.f, sq = 0.f;
    for (int i = tid; i < n / 2; i += 256) {
        float2 v = __half22float2(*(__half2*)(p + i * 2));
        s += v.x + v.y;
        sq = fmaf(v.x, v.x, fmaf(v.y, v.y, sq));
    }
    #pragma unroll
    for (int o = 16; o > 0; o >>= 1) {
        s  += __shfl_xor_sync(~0u, s, o);
        sq += __shfl_xor_sync(~0u, sq, o);
    }
    if ((tid & 31) == 0) { s8a[tid >> 5] = s; s8b[tid >> 5] = sq; }
    __syncthreads();
    s = 0.f; sq = 0.f;
    #pragma unroll
    for (int i = 0; i < 8; i++) { s += s8a[i]; sq += s8b[i]; }
    float mu = s / n;
    float var = sq / n - mu * mu;
    float rstd = rsqrtf(var + 1e-5f);

    for (int i = tid; i < n / 2; i += 256) {
        float2 v = __half22float2(*(__half2*)(p + i * 2));
        float a = (v.x - mu) * rstd * scale[i * 2]     + bias[i * 2];
        float c = (v.y - mu) * rstd * scale[i * 2 + 1] + bias[i * 2 + 1];
        a = 0.5f * a * (1.f + erff(a * 0.70710678118654752f));
        c = 0.5f * c * (1.f + erff(c * 0.70710678118654752f));
        *(__half2*)(p + i * 2) = __floats2half2_rn(a, c);
    }
}

// ---------------------------------------------------------------------------
// Host
// ---------------------------------------------------------------------------
static inline void* sym(const void* s)
{
    void* p = nullptr;
    cudaGetSymbolAddress(&p, s);
    return p;
}

extern "C" void kernel_launch(void* const* d_in, const int* in_sizes, int n_in,
                              void* d_out, int out_size)
{
    const float* x       = (const float*)d_in[0];
    const float* enc     = (const float*)d_in[1];
    const float* Wqkv_w  = (const float*)d_in[2];
    const float* Wqkv_b  = (const float*)d_in[3];
    const float* out_w   = (const float*)d_in[4];
    const float* out_b   = (const float*)d_in[5];
    const float* ffn0_w  = (const float*)d_in[6];
    const float* ffn0_b  = (const float*)d_in[7];
    const float* ln_s    = (const float*)d_in[8];
    const float* ln_b    = (const float*)d_in[9];
    const float* ffn3_w  = (const float*)d_in[10];
    const float* ffn3_b  = (const float*)d_in[11];
    float* out = (float*)d_out;

    __half* xr    = (__half*)sym(g_xr);
    __half* qkv   = (__half*)sym(g_qkv);
    __half* q     = (__half*)sym(g_q);
    __half* k     = (__half*)sym(g_k);
    __half* v     = (__half*)sym(g_v);
    __half* msgin = (__half*)sym(g_msgin);
    __half* msg   = (__half*)sym(g_msg);
    __half* hbuf  = (__half*)sym(g_h);
    __half* wqkvT = (__half*)sym(g_wqkvT);
    __half* woutT = (__half*)sym(g_woutT);
    __half* w0T   = (__half*)sym(g_w0T);
    __half* w3T   = (__half*)sym(g_w3T);

    static bool attr_done = false;
    if (!attr_done) {
        cudaFuncSetAttribute(flash_kernel,
            cudaFuncAttributeMaxDynamicSharedMemorySize, FL_SMEM_BYTES);
        cudaFuncSetAttribute(hgemm<0>,
            cudaFuncAttributeMaxDynamicSharedMemorySize, GEMM_SMEM);
        cudaFuncSetAttribute(hgemm<1>,
            cudaFuncAttributeMaxDynamicSharedMemorySize, GEMM_SMEM);
        attr_done = true;
    }

    // 0. prologue: round + transpose weights, round x
    wt_round_T<<<dim3(3 * DIM / 32, DIM / 32), dim3(32, 8)>>>(Wqkv_w, wqkvT, DIM, 3 * DIM);
    wt_round_T<<<dim3(DIM / 32, DIM / 32), dim3(32, 8)>>>(out_w, woutT, DIM, DIM);
    wt_round_T<<<dim3(2 * DIM / 32, 2 * DIM / 32), dim3(32, 8)>>>(ffn0_w, w0T, 2 * DIM, 2 * DIM);
    wt_round_T<<<dim3(DIM / 32, 2 * DIM / 32), dim3(32, 8)>>>(ffn3_w, w3T, 2 * DIM, DIM);
    x_round_kernel<<<(MTOK * DIM / 2 + 255) / 256, 256>>>(x);

    // 1. QKV projection: [8192,1024] x [3072,1024]^T -> half
    hgemm<1><<<dim3(3 * DIM / 128, MTOK / 128), 256, GEMM_SMEM>>>(
        xr, nullptr, wqkvT, Wqkv_b, nullptr, qkv, DIM, DIM, DIM, 0, 3 * DIM);

    // 2. RoPE + split
    {
        size_t total = (size_t)BB * NH * NSEQ * (HD / 2);
        rope_split_kernel<<<(unsigned)((total + 255) / 256), 256>>>(qkv, enc);
    }

    // 3. Flash attention -> msgin[b,n,h*hd] (half)
    flash_kernel<<<dim3(NSEQ / 128, BHN), 256, FL_SMEM_BYTES>>>(
        q, k, v, msgin);

    // 4. out projection -> msg (half)
    hgemm<1><<<dim3(DIM / 128, MTOK / 128), 256, GEMM_SMEM>>>(
        msgin, nullptr, woutT, out_b, nullptr, msg, DIM, DIM, DIM, 0, DIM);

    // 5. FFN0 with fused concat: A = [xr | msg] -> hbuf (half)
    hgemm<1><<<dim3(2 * DIM / 128, MTOK / 128), 256, GEMM_SMEM>>>(
        xr, msg, w0T, ffn0_b, nullptr, hbuf, 2 * DIM, DIM, DIM, DIM, 2 * DIM);

    // 6. LayerNorm + GELU (in place on half)
    ln_gelu_kernel<<<MTOK, 256>>>(ln_s, ln_b);

    // 7. FFN3 + residual fused: out = hbuf*W3 + b3 + x  (float out)
    hgemm<0><<<dim3(DIM / 128, MTOK / 128), 256, GEMM_SMEM>>>(
        hbuf, nullptr, w3T, ffn3_b, x, out, 2 * DIM, 2 * DIM, 2 * DIM, 0, DIM);
}

// round 9
// speedup vs baseline: 8.9227x; 1.0149x over previous
#include <cuda_runtime.h>
#include <cuda_fp16.h>
#include <math.h>
#include <stdint.h>

// Problem constants
#define BB    4
#define NSEQ  2048
#define DIM   1024
#define NH    16
#define HD    64
#define MTOK  (BB*NSEQ)      // 8192 tokens
#define BHN   (BB*NH)        // 64 batch*heads

// ---------------------------------------------------------------------------
// Static device scratch (fp16 activations/weights)
// ---------------------------------------------------------------------------
__device__ __half g_xr    [(size_t)MTOK * DIM];
__device__ __half g_qkv   [(size_t)MTOK * 3 * DIM];
__device__ __half g_q     [(size_t)BHN * NSEQ * HD];
__device__ __half g_k     [(size_t)BHN * NSEQ * HD];
__device__ __half g_v     [(size_t)BHN * NSEQ * HD];
__device__ __half g_msgin [(size_t)MTOK * DIM];
__device__ __half g_h     [(size_t)MTOK * 2 * DIM];
// weights
__device__ __half g_wqkvT [(size_t)(3*DIM) * DIM];   // [N][K]
__device__ __half g_woutNT[(size_t)DIM * DIM];       // out_w row-major [d][e]
__device__ __half g_w0T   [(size_t)(2*DIM) * (2*DIM)];  // [N][K]: k<1024 W0_top, k>=1024 Wf
__device__ __half g_wf    [(size_t)(2*DIM) * DIM];   // Wf^T scratch [n][d]
__device__ __half g_w3T   [(size_t)DIM * (2*DIM)];
__device__ float  g_b0f   [2*DIM];                   // fused FFN0 bias

// ---------------------------------------------------------------------------
// helpers
// ---------------------------------------------------------------------------
__device__ __forceinline__ void mma16(float c[4], const unsigned a[4],
                                      unsigned b0, unsigned b1)
{
    asm volatile(
        "mma.sync.aligned.m16n8k16.row.col.f32.f16.f16.f32 "
        "{%0,%1,%2,%3}, {%4,%5,%6,%7}, {%8,%9}, {%0,%1,%2,%3};"
        : "+f"(c[0]), "+f"(c[1]), "+f"(c[2]), "+f"(c[3])
        : "r"(a[0]), "r"(a[1]), "r"(a[2]), "r"(a[3]), "r"(b0), "r"(b1));
}

__device__ __forceinline__ void ldsm4(unsigned &r0, unsigned &r1,
                                      unsigned &r2, unsigned &r3, const void* p)
{
    unsigned a = (unsigned)__cvta_generic_to_shared(p);
    asm volatile("ldmatrix.sync.aligned.m8n8.x4.shared.b16 {%0,%1,%2,%3}, [%4];"
                 : "=r"(r0), "=r"(r1), "=r"(r2), "=r"(r3) : "r"(a));
}

__device__ __forceinline__ void ldsm4t(unsigned &r0, unsigned &r1,
                                       unsigned &r2, unsigned &r3, const void* p)
{
    unsigned a = (unsigned)__cvta_generic_to_shared(p);
    asm volatile("ldmatrix.sync.aligned.m8n8.x4.trans.shared.b16 {%0,%1,%2,%3}, [%4];"
                 : "=r"(r0), "=r"(r1), "=r"(r2), "=r"(r3) : "r"(a));
}

__device__ __forceinline__ void cp16(void* s, const void* g)
{
    unsigned a = (unsigned)__cvta_generic_to_shared(s);
    asm volatile("cp.async.cg.shared.global [%0], [%1], 16;" :: "r"(a), "l"(g));
}
#define CP_COMMIT() asm volatile("cp.async.commit_group;")
#define CP_WAIT(n)  asm volatile("cp.async.wait_group %0;" :: "n"(n))

__device__ __forceinline__ unsigned h2bits(float a, float b)
{
    __half2 h = __floats2half2_rn(a, b);
    return *reinterpret_cast<unsigned*>(&h);
}

// ---------------------------------------------------------------------------
// fp16 GEMM: C[M,N] = [A | A2][M,K] * BT[N,K]^T (+bias) (+resid)
// BM=BN=128, BK=64 halves, 3-stage cp.async, ldmatrix x4 frags, 2 CTAs/SM.
// ---------------------------------------------------------------------------
#define GS_LDH   72
#define GS_STAGE (2 * 128 * GS_LDH)          // halves per stage
#define GEMM_SMEM (3 * GS_STAGE * 2)         // bytes

template<int OUT_HALF>
__global__ __launch_bounds__(256, 2) void hgemm(
    const __half* __restrict__ A, const __half* __restrict__ A2,
    const __half* __restrict__ BT,
    const float* __restrict__ bias, const float* __restrict__ resid,
    void* __restrict__ Cv,
    int K, int K1, int lda, int lda2, int ldc)
{
    extern __shared__ __half hs[];
    const int tid  = threadIdx.x;
    const int lane = tid & 31, warp = tid >> 5;
    const int g    = lane >> 2, tg = lane & 3;
    const int wm   = warp & 1, wn = warp >> 1;       // 2x4 warps, 64x32 tiles
    const int row0 = blockIdx.y * 128, col0 = blockIdx.x * 128;

    const int lrow = (lane & 7) + ((lane >> 3) & 1) * 8;   // A ldsm row
    const int lcol = ((lane >> 4) & 1) * 8;                // A ldsm col (halves)
    const int brow = (lane & 7) + ((lane >> 4) & 1) * 8;   // B ldsm row
    const int bcol = ((lane >> 3) & 1) * 8;                // B ldsm col

    float acc[4][4][4] = {};

    auto issue = [&](int kt) {
        int k0 = kt * 64;
        if (k0 < K) {
            __half* sa = hs + (kt % 3) * GS_STAGE;
            __half* sb = sa + 128 * GS_LDH;
            const __half* Asrc = A; int kk = k0, ld = lda;
            if (A2 && k0 >= K1) { Asrc = A2; kk = k0 - K1; ld = lda2; }
            #pragma unroll
            for (int i = 0; i < 4; i++) {
                int id = tid + i * 256;
                int r = id >> 3, c = (id & 7) * 8;
                cp16(sa + r * GS_LDH + c, Asrc + (size_t)(row0 + r) * ld + kk + c);
                cp16(sb + r * GS_LDH + c, BT + (size_t)(col0 + r) * K + k0 + c);
            }
        }
        CP_COMMIT();
    };

    auto compute = [&](int kt) {
        const __half* sa = hs + (kt % 3) * GS_STAGE;
        const __half* sb = sa + 128 * GS_LDH;
        #pragma unroll
        for (int ks = 0; ks < 4; ks++) {
            unsigned af[4][4], bf[4][2];
            #pragma unroll
            for (int mi = 0; mi < 4; mi++)
                ldsm4(af[mi][0], af[mi][1], af[mi][2], af[mi][3],
                      sa + (wm * 64 + mi * 16 + lrow) * GS_LDH + ks * 16 + lcol);
            #pragma unroll
            for (int p = 0; p < 2; p++) {
                unsigned r0, r1, r2, r3;
                ldsm4(r0, r1, r2, r3,
                      sb + (wn * 32 + p * 16 + brow) * GS_LDH + ks * 16 + bcol);
                bf[2*p][0] = r0; bf[2*p][1] = r1;
                bf[2*p+1][0] = r2; bf[2*p+1][1] = r3;
            }
            #pragma unroll
            for (int mi = 0; mi < 4; mi++)
                #pragma unroll
                for (int ni = 0; ni < 4; ni++)
                    mma16(acc[mi][ni], af[mi], bf[ni][0], bf[ni][1]);
        }
    };

    issue(0); issue(1);
    const int KT = K / 64;
    CP_WAIT(1); __syncthreads();
    for (int kt = 0; kt < KT; kt++) {
        issue(kt + 2);
        compute(kt);
        CP_WAIT(1); __syncthreads();
    }

    #pragma unroll
    for (int mi = 0; mi < 4; mi++) {
        int rb = row0 + wm * 64 + mi * 16 + g;
        #pragma unroll
        for (int ni = 0; ni < 4; ni++) {
            int cb = col0 + wn * 32 + ni * 8 + 2 * tg;
            float b0v = bias ? bias[cb]     : 0.f;
            float b1v = bias ? bias[cb + 1] : 0.f;
            float v00 = acc[mi][ni][0] + b0v, v01 = acc[mi][ni][1] + b1v;
            float v10 = acc[mi][ni][2] + b0v, v11 = acc[mi][ni][3] + b1v;
            if (OUT_HALF) {
                __half* C = (__half*)Cv;
                *(__half2*)(C + (size_t)rb * ldc + cb) = __floats2half2_rn(v00, v01);
                *(__half2*)(C + (size_t)(rb + 8) * ldc + cb) = __floats2half2_rn(v10, v11);
            } else {
                float* C = (float*)Cv;
                v00 += resid[(size_t)rb * ldc + cb];
                v01 += resid[(size_t)rb * ldc + cb + 1];
                v10 += resid[(size_t)(rb + 8) * ldc + cb];
                v11 += resid[(size_t)(rb + 8) * ldc + cb + 1];
                *(float2*)(C + (size_t)rb * ldc + cb)       = make_float2(v00, v01);
                *(float2*)(C + (size_t)(rb + 8) * ldc + cb) = make_float2(v10, v11);
            }
        }
    }
}

// ---------------------------------------------------------------------------
// Weight prep
// ---------------------------------------------------------------------------
// out[N][K] = fp16(in[K][N]) transpose
__global__ void wt_round_T(const float* __restrict__ in, __half* __restrict__ out,
                           int K, int N)
{
    __shared__ float t[32][33];
    int n0 = blockIdx.x * 32, k0 = blockIdx.y * 32;
    int tx = threadIdx.x, ty = threadIdx.y;
    #pragma unroll
    for (int i = 0; i < 32; i += 8)
        t[ty + i][tx] = in[(size_t)(k0 + ty + i) * N + n0 + tx];
    __syncthreads();
    #pragma unroll
    for (int i = 0; i < 32; i += 8)
        out[(size_t)(n0 + ty + i) * K + k0 + tx] = __float2half_rn(t[tx][ty + i]);
}

// dst (half) = fp16(src float), n even
__global__ void round_copy(const float* __restrict__ src, __half* __restrict__ dst,
                           size_t n2)
{
    size_t idx = (size_t)blockIdx.x * blockDim.x + threadIdx.x;
    if (idx >= n2) return;
    float2 v = *(const float2*)(src + idx * 2);
    *(__half2*)(dst + idx * 2) = __floats2half2_rn(v.x, v.y);
}

// copy Wf^T scratch [2048][1024] into w0T[:, 1024:2048]
__global__ void copy_wf()
{
    size_t idx = (size_t)blockIdx.x * blockDim.x + threadIdx.x;   // half2 units
    if (idx >= (size_t)(2 * DIM) * DIM / 2) return;
    size_t n = idx / (DIM / 2);
    size_t d2 = idx % (DIM / 2);
    *(__half2*)(g_w0T + n * (2 * DIM) + DIM + d2 * 2) =
        *(__half2*)(g_wf + n * DIM + d2 * 2);
}

// fused bias: b0f[n] = ffn0_b[n] + sum_e out_b[e] * ffn0_w[(1024+e)*2048 + n]
__global__ void bias_fuse(const float* __restrict__ ffn0_b,
                          const float* __restrict__ out_b,
                          const float* __restrict__ ffn0_w)
{
    int n = blockIdx.x * 256 + threadIdx.x;
    float acc = ffn0_b[n];
    for (int e = 0; e < DIM; e++)
        acc = fmaf(out_b[e], ffn0_w[(size_t)(DIM + e) * (2 * DIM) + n], acc);
    g_b0f[n] = acc;
}

// ---------------------------------------------------------------------------
// Flash attention, fp16 mma m16n8k16, HD=64, cp.async double-buffered K/V.
// P stays in registers (S C-frag == PV A-frag after half2 packing).
// smem layout (halves):
//   [0, 9216)        Qs [128][72]
//   [9216, 46080)    2 x (Ks [128][72] + Vs [128][72])
// Total 46080 halves = 92160 B.
// ---------------------------------------------------------------------------
#define FL_KV_OFF   9216
#define FL_SMEM_BYTES (46080 * 2)

__global__ __launch_bounds__(256, 1) void flash_kernel(
    const __half* __restrict__ Q, const __half* __restrict__ K,
    const __half* __restrict__ V, __half* __restrict__ O)
{
    extern __shared__ __half sm[];

    const int tid  = threadIdx.x;
    const int w    = tid >> 5, lane = tid & 31;
    const int g    = lane >> 2, tg = lane & 3;
    const int bh   = blockIdx.y;
    const int q0   = blockIdx.x * 128;
    const int b    = bh >> 4, h = bh & 15;

    const int lrow = (lane & 7) + ((lane >> 3) & 1) * 8;
    const int lcol = ((lane >> 4) & 1) * 8;
    const int brow = (lane & 7) + ((lane >> 4) & 1) * 8;
    const int bcol = ((lane >> 3) & 1) * 8;

    const __half* Qp = Q + (size_t)bh * NSEQ * HD;
    const __half* Kp = K + (size_t)bh * NSEQ * HD;
    const __half* Vp = V + (size_t)bh * NSEQ * HD;

    auto issue = [&](int j) {
        __half* Kb = sm + FL_KV_OFF + (j & 1) * 18432;
        __half* Vb = Kb + 9216;
        #pragma unroll
        for (int i = 0; i < 4; i++) {
            int id = tid + i * 256;
            int r = id >> 3, c = (id & 7) * 8;
            size_t go = (size_t)(j * 128 + r) * HD + c;
            cp16(Kb + r * 72 + c, Kp + go);
            cp16(Vb + r * 72 + c, Vp + go);
        }
        CP_COMMIT();
    };

    issue(0);

    // ---- stage Q tile (plain loads), extract per-warp A-frags ----
    #pragma unroll
    for (int i = 0; i < 4; i++) {
        int id = tid + i * 256;
        int r = id >> 3, c = (id & 7) * 8;
        *(uint4*)(sm + r * 72 + c) = *(const uint4*)(Qp + (size_t)(q0 + r) * HD + c);
    }
    __syncthreads();
    unsigned qf[4][4];
    #pragma unroll
    for (int ks = 0; ks < 4; ks++)
        ldsm4(qf[ks][0], qf[ks][1], qf[ks][2], qf[ks][3],
              sm + (w * 16 + lrow) * 72 + ks * 16 + lcol);

    float m0 = -1e30f, m1 = -1e30f, l0 = 0.f, l1 = 0.f;
    float oa[8][4] = {};

    for (int j = 0; j < 16; j++) {
        if (j < 15) { issue(j + 1); CP_WAIT(1); }
        else        { CP_WAIT(0); }
        __syncthreads();

        const __half* Ks = sm + FL_KV_OFF + (j & 1) * 18432;
        const __half* Vs = Ks + 9216;

        // ---- S = Q K^T (16 q rows x 128 kv per warp) ----
        float s[16][4];
        #pragma unroll
        for (int ni = 0; ni < 16; ni++)
            s[ni][0] = s[ni][1] = s[ni][2] = s[ni][3] = 0.f;
        #pragma unroll
        for (int ks = 0; ks < 4; ks++) {
            #pragma unroll
            for (int n2 = 0; n2 < 8; n2++) {
                unsigned r0, r1, r2, r3;
                ldsm4(r0, r1, r2, r3,
                      Ks + (n2 * 16 + brow) * 72 + ks * 16 + bcol);
                mma16(s[2*n2],     qf[ks], r0, r1);
                mma16(s[2*n2 + 1], qf[ks], r2, r3);
            }
        }

        // ---- online softmax ----
        float mt0 = -1e30f, mt1 = -1e30f;
        #pragma unroll
        for (int ni = 0; ni < 16; ni++) {
            s[ni][0] *= 0.125f; s[ni][1] *= 0.125f;
            s[ni][2] *= 0.125f; s[ni][3] *= 0.125f;
            mt0 = fmaxf(mt0, fmaxf(s[ni][0], s[ni][1]));
            mt1 = fmaxf(mt1, fmaxf(s[ni][2], s[ni][3]));
        }
        mt0 = fmaxf(mt0, __shfl_xor_sync(~0u, mt0, 1));
        mt0 = fmaxf(mt0, __shfl_xor_sync(~0u, mt0, 2));
        mt1 = fmaxf(mt1, __shfl_xor_sync(~0u, mt1, 1));
        mt1 = fmaxf(mt1, __shfl_xor_sync(~0u, mt1, 2));
        float m0n = fmaxf(m0, mt0), m1n = fmaxf(m1, mt1);
        float c0 = __expf(m0 - m0n), c1 = __expf(m1 - m1n);
        float rs0 = 0.f, rs1 = 0.f;
        #pragma unroll
        for (int ni = 0; ni < 16; ni++) {
            s[ni][0] = __expf(s[ni][0] - m0n);
            s[ni][1] = __expf(s[ni][1] - m0n);
            s[ni][2] = __expf(s[ni][2] - m1n);
            s[ni][3] = __expf(s[ni][3] - m1n);
            rs0 += s[ni][0] + s[ni][1];
            rs1 += s[ni][2] + s[ni][3];
        }
        rs0 += __shfl_xor_sync(~0u, rs0, 1); rs0 += __shfl_xor_sync(~0u, rs0, 2);
        rs1 += __shfl_xor_sync(~0u, rs1, 1); rs1 += __shfl_xor_sync(~0u, rs1, 2);
        l0 = l0 * c0 + rs0; l1 = l1 * c1 + rs1;
        m0 = m0n; m1 = m1n;
        #pragma unroll
        for (int ni = 0; ni < 8; ni++) {
            oa[ni][0] *= c0; oa[ni][1] *= c0;
            oa[ni][2] *= c1; oa[ni][3] *= c1;
        }

        // ---- O += P V  (P packed directly from S fragments) ----
        #pragma unroll
        for (int c = 0; c < 8; c++) {
            unsigned a[4];
            a[0] = h2bits(s[2*c][0],     s[2*c][1]);
            a[1] = h2bits(s[2*c][2],     s[2*c][3]);
            a[2] = h2bits(s[2*c + 1][0], s[2*c + 1][1]);
            a[3] = h2bits(s[2*c + 1][2], s[2*c + 1][3]);
            #pragma unroll
            for (int n2 = 0; n2 < 4; n2++) {
                unsigned r0, r1, r2, r3;
                ldsm4t(r0, r1, r2, r3,
                       Vs + (c * 16 + lrow) * 72 + n2 * 16 + lcol);
                mma16(oa[2*n2],     a, r0, r1);
                mma16(oa[2*n2 + 1], a, r2, r3);
            }
        }
        __syncthreads();
    }

    // ---- epilogue: O / l -> msgin[b, q, h*64+hd] (fp16) ----
    float i0 = 1.f / l0, i1 = 1.f / l1;
    int r0 = q0 + w * 16 + g, r1 = r0 + 8;
    __half* Op = O + ((size_t)b * NSEQ) * DIM + h * HD;
    #pragma unroll
    for (int ni = 0; ni < 8; ni++) {
        int cb = ni * 8 + 2 * tg;
        *(__half2*)(Op + (size_t)r0 * DIM + cb) =
            __floats2half2_rn(oa[ni][0] * i0, oa[ni][1] * i0);
        *(__half2*)(Op + (size_t)r1 * DIM + cb) =
            __floats2half2_rn(oa[ni][2] * i1, oa[ni][3] * i1);
    }
}

// ---------------------------------------------------------------------------
// RoPE + QKV split (half in, half out)
// ---------------------------------------------------------------------------
__global__ void rope_split_kernel(const __half* __restrict__ qkv,
                                  const float* __restrict__ enc)
{
    size_t idx = (size_t)blockIdx.x * blockDim.x + threadIdx.x;
    const size_t total = (size_t)BB * NH * NSEQ * (HD / 2);
    if (idx >= total) return;
    int pair = idx & 31;
    size_t t = idx >> 5;
    int n = t & (NSEQ - 1); t >>= 11;
    int h = t & (NH - 1);
    int b = (int)(t >> 4);

    const __half* src = qkv + ((size_t)(b * NSEQ + n) * (3 * DIM)
                               + h * (HD * 3) + pair * 6);
    float q0 = __half2float(src[0]), k0 = __half2float(src[1]);
    float v0 = __half2float(src[2]), q1 = __half2float(src[3]);
    float k1 = __half2float(src[4]), v1 = __half2float(src[5]);

    const float* e0 = enc + (size_t)n * HD + pair * 2;
    const float* e1 = enc + (size_t)NSEQ * HD + (size_t)n * HD + pair * 2;
    float f00 = e0[0], f01 = e0[1], f10 = e1[0], f11 = e1[1];

    size_t o = ((size_t)(b * NH + h) * NSEQ + n) * HD + pair * 2;
    *(__half2*)(g_q + o) = __floats2half2_rn(q0 * f00 - q1 * f10,
                                             q1 * f01 + q0 * f11);
    *(__half2*)(g_k + o) = __floats2half2_rn(k0 * f00 - k1 * f10,
                                             k1 * f01 + k0 * f11);
    *(__half2*)(g_v + o) = __floats2half2_rn(v0, v1);
}

// LayerNorm (2048) + exact GELU, in place on g_h (half).
__global__ __launch_bounds__(256) void ln_gelu_kernel(const float* __restrict__ scale,
                                                      const float* __restrict__ bias)
{
    const int n = 2 * DIM;
    __half* p = g_h + (size_t)blockIdx.x * n;
    const int tid = threadIdx.x;
    __shared__ float s8a[8], s8b[8];

    float s = 0.f, sq = 0.f;
    for (int i = tid; i < n / 2; i += 256) {
        float2 v = __half22float2(*(__half2*)(p + i * 2));
        s += v.x + v.y;
        sq = fmaf(v.x, v.x, fmaf(v.y, v.y, sq));
    }
    #pragma unroll
    for (int o = 16; o > 0; o >>= 1) {
        s  += __shfl_xor_sync(~0u, s, o);
        sq += __shfl_xor_sync(~0u, sq, o);
    }
    if ((tid & 31) == 0) { s8a[tid >> 5] = s; s8b[tid >> 5] = sq; }
    __syncthreads();
    s = 0.f; sq = 0.f;
    #pragma unroll
    for (int i = 0; i < 8; i++) { s += s8a[i]; sq += s8b[i]; }
    float mu = s / n;
    float var = sq / n - mu * mu;
    float rstd = rsqrtf(var + 1e-5f);

    for (int i = tid; i < n / 2; i += 256) {
        float2 v = __half22float2(*(__half2*)(p + i * 2));
        float a = (v.x - mu) * rstd * scale[i * 2]     + bias[i * 2];
        float c = (v.y - mu) * rstd * scale[i * 2 + 1] + bias[i * 2 + 1];
        a = 0.5f * a * (1.f + erff(a * 0.70710678118654752f));
        c = 0.5f * c * (1.f + erff(c * 0.70710678118654752f));
        *(__half2*)(p + i * 2) = __floats2half2_rn(a, c);
    }
}

// ---------------------------------------------------------------------------
// Host
// ---------------------------------------------------------------------------
static inline void* sym(const void* s)
{
    void* p = nullptr;
    cudaGetSymbolAddress(&p, s);
    return p;
}

extern "C" void kernel_launch(void* const* d_in, const int* in_sizes, int n_in,
                              void* d_out, int out_size)
{
    const float* x       = (const float*)d_in[0];
    const float* enc     = (const float*)d_in[1];
    const float* Wqkv_w  = (const float*)d_in[2];
    const float* Wqkv_b  = (const float*)d_in[3];
    const float* out_w   = (const float*)d_in[4];
    const float* out_b   = (const float*)d_in[5];
    const float* ffn0_w  = (const float*)d_in[6];
    const float* ffn0_b  = (const float*)d_in[7];
    const float* ln_s    = (const float*)d_in[8];
    const float* ln_b    = (const float*)d_in[9];
    const float* ffn3_w  = (const float*)d_in[10];
    const float* ffn3_b  = (const float*)d_in[11];
    float* out = (float*)d_out;

    __half* xr     = (__half*)sym(g_xr);
    __half* qkv    = (__half*)sym(g_qkv);
    __half* q      = (__half*)sym(g_q);
    __half* k      = (__half*)sym(g_k);
    __half* v      = (__half*)sym(g_v);
    __half* msgin  = (__half*)sym(g_msgin);
    __half* hbuf   = (__half*)sym(g_h);
    __half* wqkvT  = (__half*)sym(g_wqkvT);
    __half* woutNT = (__half*)sym(g_woutNT);
    __half* w0T    = (__half*)sym(g_w0T);
    __half* wf     = (__half*)sym(g_wf);
    __half* w3T    = (__half*)sym(g_w3T);
    float*  b0f    = (float*)sym(g_b0f);

    static bool attr_done = false;
    if (!attr_done) {
        cudaFuncSetAttribute(flash_kernel,
            cudaFuncAttributeMaxDynamicSharedMemorySize, FL_SMEM_BYTES);
        cudaFuncSetAttribute(hgemm<0>,
            cudaFuncAttributeMaxDynamicSharedMemorySize, GEMM_SMEM);
        cudaFuncSetAttribute(hgemm<1>,
            cudaFuncAttributeMaxDynamicSharedMemorySize, GEMM_SMEM);
        attr_done = true;
    }

    // 0. prologue: round weights / x
    wt_round_T<<<dim3(3 * DIM / 32, DIM / 32), dim3(32, 8)>>>(Wqkv_w, wqkvT, DIM, 3 * DIM);
    wt_round_T<<<dim3(2 * DIM / 32, 2 * DIM / 32), dim3(32, 8)>>>(ffn0_w, w0T, 2 * DIM, 2 * DIM);
    wt_round_T<<<dim3(DIM / 32, 2 * DIM / 32), dim3(32, 8)>>>(ffn3_w, w3T, 2 * DIM, DIM);
    round_copy<<<(DIM * DIM / 2 + 255) / 256, 256>>>(out_w, woutNT, (size_t)DIM * DIM / 2);
    round_copy<<<((size_t)MTOK * DIM / 2 + 255) / 256, 256>>>(x, xr, (size_t)MTOK * DIM / 2);

    // 0b. weight fusion: Wf^T[n,d] = sum_e w0T[n,1024+e] * out_w[d,e]
    hgemm<1><<<dim3(DIM / 128, 2 * DIM / 128), 256, GEMM_SMEM>>>(
        w0T + DIM, nullptr, woutNT, nullptr, nullptr, wf,
        DIM, DIM, 2 * DIM, 0, DIM);
    copy_wf<<<((size_t)(2 * DIM) * DIM / 2 + 255) / 256, 256>>>();
    bias_fuse<<<2 * DIM / 256, 256>>>(ffn0_b, out_b, ffn0_w);

    // 1. QKV projection: [8192,1024] x [3072,1024]^T -> half
    hgemm<1><<<dim3(3 * DIM / 128, MTOK / 128), 256, GEMM_SMEM>>>(
        xr, nullptr, wqkvT, Wqkv_b, nullptr, qkv, DIM, DIM, DIM, 0, 3 * DIM);

    // 2. RoPE + split
    {
        size_t total = (size_t)BB * NH * NSEQ * (HD / 2);
        rope_split_kernel<<<(unsigned)((total + 255) / 256), 256>>>(qkv, enc);
    }

    // 3. Flash attention -> msgin[b,n,h*hd] (half)
    flash_kernel<<<dim3(NSEQ / 128, BHN), 256, FL_SMEM_BYTES>>>(
        q, k, v, msgin);

    // 4. FFN0 (out-proj folded in): h = [xr | ctx] * [W0_top | Wf]^T + b0f
    hgemm<1><<<dim3(2 * DIM / 128, MTOK / 128), 256, GEMM_SMEM>>>(
        xr, msgin, w0T, b0f, nullptr, hbuf, 2 * DIM, DIM, DIM, DIM, 2 * DIM);

    // 5. LayerNorm + GELU (in place on half)
    ln_gelu_kernel<<<MTOK, 256>>>(ln_s, ln_b);

    // 6. FFN3 + residual fused: out = hbuf*W3 + b3 + x  (float out)
    hgemm<0><<<dim3(DIM / 128, MTOK / 128), 256, GEMM_SMEM>>>(
        hbuf, nullptr, w3T, ffn3_b, x, out, 2 * DIM, 2 * DIM, 2 * DIM, 0, DIM);
}

// round 10
// speedup vs baseline: 9.8584x; 1.1049x over previous
#include <cuda_runtime.h>
#include <cuda_fp16.h>
#include <math.h>
#include <stdint.h>

// Problem constants
#define BB    4
#define NSEQ  2048
#define DIM   1024
#define NH    16
#define HD    64
#define MTOK  (BB*NSEQ)      // 8192 tokens
#define BHN   (BB*NH)        // 64 batch*heads

// ---------------------------------------------------------------------------
// Static device scratch (fp16 activations/weights)
// ---------------------------------------------------------------------------
__device__ __half g_xr    [(size_t)MTOK * DIM];
__device__ __half g_qkv   [(size_t)MTOK * 3 * DIM];
__device__ __half g_q     [(size_t)BHN * NSEQ * HD];
__device__ __half g_k     [(size_t)BHN * NSEQ * HD];
__device__ __half g_v     [(size_t)BHN * NSEQ * HD];
__device__ __half g_msgin [(size_t)MTOK * DIM];
__device__ __half g_h     [(size_t)MTOK * 2 * DIM];
// weights
__device__ __half g_wqkvT [(size_t)(3*DIM) * DIM];   // [N][K]
__device__ __half g_woutNT[(size_t)DIM * DIM];       // out_w row-major [d][e]
__device__ __half g_w0T   [(size_t)(2*DIM) * (2*DIM)];  // [N][K]: k<1024 W0_top, k>=1024 Wf
__device__ __half g_wf    [(size_t)(2*DIM) * DIM];   // Wf^T scratch [n][d]
__device__ __half g_w3T   [(size_t)DIM * (2*DIM)];
__device__ float  g_b0f   [2*DIM];                   // fused FFN0 bias

// ---------------------------------------------------------------------------
// helpers
// ---------------------------------------------------------------------------
__device__ __forceinline__ void mma16(float c[4], const unsigned a[4],
                                      unsigned b0, unsigned b1)
{
    asm volatile(
        "mma.sync.aligned.m16n8k16.row.col.f32.f16.f16.f32 "
        "{%0,%1,%2,%3}, {%4,%5,%6,%7}, {%8,%9}, {%0,%1,%2,%3};"
        : "+f"(c[0]), "+f"(c[1]), "+f"(c[2]), "+f"(c[3])
        : "r"(a[0]), "r"(a[1]), "r"(a[2]), "r"(a[3]), "r"(b0), "r"(b1));
}

__device__ __forceinline__ void ldsm4(unsigned &r0, unsigned &r1,
                                      unsigned &r2, unsigned &r3, const void* p)
{
    unsigned a = (unsigned)__cvta_generic_to_shared(p);
    asm volatile("ldmatrix.sync.aligned.m8n8.x4.shared.b16 {%0,%1,%2,%3}, [%4];"
                 : "=r"(r0), "=r"(r1), "=r"(r2), "=r"(r3) : "r"(a));
}

__device__ __forceinline__ void ldsm4t(unsigned &r0, unsigned &r1,
                                       unsigned &r2, unsigned &r3, const void* p)
{
    unsigned a = (unsigned)__cvta_generic_to_shared(p);
    asm volatile("ldmatrix.sync.aligned.m8n8.x4.trans.shared.b16 {%0,%1,%2,%3}, [%4];"
                 : "=r"(r0), "=r"(r1), "=r"(r2), "=r"(r3) : "r"(a));
}

__device__ __forceinline__ void cp16(void* s, const void* g)
{
    unsigned a = (unsigned)__cvta_generic_to_shared(s);
    asm volatile("cp.async.cg.shared.global [%0], [%1], 16;" :: "r"(a), "l"(g));
}
#define CP_COMMIT() asm volatile("cp.async.commit_group;")
#define CP_WAIT(n)  asm volatile("cp.async.wait_group %0;" :: "n"(n))

__device__ __forceinline__ unsigned h2bits(float a, float b)
{
    __half2 h = __floats2half2_rn(a, b);
    return *reinterpret_cast<unsigned*>(&h);
}

// ---------------------------------------------------------------------------
// fp16 GEMM: C[M,N] = [A | A2][M,K] * BT[N,K]^T (+bias) (+resid)
// BM=BN=128, BK=64 halves, 3-stage cp.async, ldmatrix x4 frags, 2 CTAs/SM.
// ---------------------------------------------------------------------------
#define GS_LDH   72
#define GS_STAGE (2 * 128 * GS_LDH)          // halves per stage
#define GEMM_SMEM (3 * GS_STAGE * 2)         // bytes

template<int OUT_HALF>
__global__ __launch_bounds__(256, 2) void hgemm(
    const __half* __restrict__ A, const __half* __restrict__ A2,
    const __half* __restrict__ BT,
    const float* __restrict__ bias, const float* __restrict__ resid,
    void* __restrict__ Cv,
    int K, int K1, int lda, int lda2, int ldc)
{
    extern __shared__ __half hs[];
    const int tid  = threadIdx.x;
    const int lane = tid & 31, warp = tid >> 5;
    const int g    = lane >> 2, tg = lane & 3;
    const int wm   = warp & 1, wn = warp >> 1;       // 2x4 warps, 64x32 tiles
    const int row0 = blockIdx.y * 128, col0 = blockIdx.x * 128;

    const int lrow = (lane & 7) + ((lane >> 3) & 1) * 8;   // A ldsm row
    const int lcol = ((lane >> 4) & 1) * 8;                // A ldsm col (halves)
    const int brow = (lane & 7) + ((lane >> 4) & 1) * 8;   // B ldsm row
    const int bcol = ((lane >> 3) & 1) * 8;                // B ldsm col

    float acc[4][4][4] = {};

    auto issue = [&](int kt) {
        int k0 = kt * 64;
        if (k0 < K) {
            __half* sa = hs + (kt % 3) * GS_STAGE;
            __half* sb = sa + 128 * GS_LDH;
            const __half* Asrc = A; int kk = k0, ld = lda;
            if (A2 && k0 >= K1) { Asrc = A2; kk = k0 - K1; ld = lda2; }
            #pragma unroll
            for (int i = 0; i < 4; i++) {
                int id = tid + i * 256;
                int r = id >> 3, c = (id & 7) * 8;
                cp16(sa + r * GS_LDH + c, Asrc + (size_t)(row0 + r) * ld + kk + c);
                cp16(sb + r * GS_LDH + c, BT + (size_t)(col0 + r) * K + k0 + c);
            }
        }
        CP_COMMIT();
    };

    auto compute = [&](int kt) {
        const __half* sa = hs + (kt % 3) * GS_STAGE;
        const __half* sb = sa + 128 * GS_LDH;
        #pragma unroll
        for (int ks = 0; ks < 4; ks++) {
            unsigned af[4][4], bf[4][2];
            #pragma unroll
            for (int mi = 0; mi < 4; mi++)
                ldsm4(af[mi][0], af[mi][1], af[mi][2], af[mi][3],
                      sa + (wm * 64 + mi * 16 + lrow) * GS_LDH + ks * 16 + lcol);
            #pragma unroll
            for (int p = 0; p < 2; p++) {
                unsigned r0, r1, r2, r3;
                ldsm4(r0, r1, r2, r3,
                      sb + (wn * 32 + p * 16 + brow) * GS_LDH + ks * 16 + bcol);
                bf[2*p][0] = r0; bf[2*p][1] = r1;
                bf[2*p+1][0] = r2; bf[2*p+1][1] = r3;
            }
            #pragma unroll
            for (int mi = 0; mi < 4; mi++)
                #pragma unroll
                for (int ni = 0; ni < 4; ni++)
                    mma16(acc[mi][ni], af[mi], bf[ni][0], bf[ni][1]);
        }
    };

    issue(0); issue(1);
    const int KT = K / 64;
    CP_WAIT(1); __syncthreads();
    for (int kt = 0; kt < KT; kt++) {
        issue(kt + 2);
        compute(kt);
        CP_WAIT(1); __syncthreads();
    }

    #pragma unroll
    for (int mi = 0; mi < 4; mi++) {
        int rb = row0 + wm * 64 + mi * 16 + g;
        #pragma unroll
        for (int ni = 0; ni < 4; ni++) {
            int cb = col0 + wn * 32 + ni * 8 + 2 * tg;
            float b0v = bias ? bias[cb]     : 0.f;
            float b1v = bias ? bias[cb + 1] : 0.f;
            float v00 = acc[mi][ni][0] + b0v, v01 = acc[mi][ni][1] + b1v;
            float v10 = acc[mi][ni][2] + b0v, v11 = acc[mi][ni][3] + b1v;
            if (OUT_HALF) {
                __half* C = (__half*)Cv;
                *(__half2*)(C + (size_t)rb * ldc + cb) = __floats2half2_rn(v00, v01);
                *(__half2*)(C + (size_t)(rb + 8) * ldc + cb) = __floats2half2_rn(v10, v11);
            } else {
                float* C = (float*)Cv;
                v00 += resid[(size_t)rb * ldc + cb];
                v01 += resid[(size_t)rb * ldc + cb + 1];
                v10 += resid[(size_t)(rb + 8) * ldc + cb];
                v11 += resid[(size_t)(rb + 8) * ldc + cb + 1];
                *(float2*)(C + (size_t)rb * ldc + cb)       = make_float2(v00, v01);
                *(float2*)(C + (size_t)(rb + 8) * ldc + cb) = make_float2(v10, v11);
            }
        }
    }
}

// ---------------------------------------------------------------------------
// Weight prep
// ---------------------------------------------------------------------------
__global__ void wt_round_T(const float* __restrict__ in, __half* __restrict__ out,
                           int K, int N)
{
    __shared__ float t[32][33];
    int n0 = blockIdx.x * 32, k0 = blockIdx.y * 32;
    int tx = threadIdx.x, ty = threadIdx.y;
    #pragma unroll
    for (int i = 0; i < 32; i += 8)
        t[ty + i][tx] = in[(size_t)(k0 + ty + i) * N + n0 + tx];
    __syncthreads();
    #pragma unroll
    for (int i = 0; i < 32; i += 8)
        out[(size_t)(n0 + ty + i) * K + k0 + tx] = __float2half_rn(t[tx][ty + i]);
}

__global__ void round_copy(const float* __restrict__ src, __half* __restrict__ dst,
                           size_t n2)
{
    size_t idx = (size_t)blockIdx.x * blockDim.x + threadIdx.x;
    if (idx >= n2) return;
    float2 v = *(const float2*)(src + idx * 2);
    *(__half2*)(dst + idx * 2) = __floats2half2_rn(v.x, v.y);
}

// copy Wf^T scratch [2048][1024] into w0T[:, 1024:2048]
__global__ void copy_wf()
{
    size_t idx = (size_t)blockIdx.x * blockDim.x + threadIdx.x;   // half2 units
    if (idx >= (size_t)(2 * DIM) * DIM / 2) return;
    size_t n = idx / (DIM / 2);
    size_t d2 = idx % (DIM / 2);
    *(__half2*)(g_w0T + n * (2 * DIM) + DIM + d2 * 2) =
        *(__half2*)(g_wf + n * DIM + d2 * 2);
}

// fused bias: b0f[n] = ffn0_b[n] + sum_e out_b[e] * ffn0_w[(1024+e)*2048 + n]
__global__ void bias_fuse(const float* __restrict__ ffn0_b,
                          const float* __restrict__ out_b,
                          const float* __restrict__ ffn0_w)
{
    int n = blockIdx.x * 256 + threadIdx.x;
    float acc = ffn0_b[n];
    for (int e = 0; e < DIM; e++)
        acc = fmaf(out_b[e], ffn0_w[(size_t)(DIM + e) * (2 * DIM) + n], acc);
    g_b0f[n] = acc;
}

// ---------------------------------------------------------------------------
// Flash attention, fp16 mma m16n8k16, HD=64, cp.async double-buffered K/V.
// P in registers; S/PV processed in two 64-col KV chunks (regs <= 128 so the
// kernel runs 2 CTAs/SM = 16 warps, matching the GEMM occupancy).
// smem (halves): Qs [128][72]; 2 x (Ks [128][72] + Vs [128][72]).
// ---------------------------------------------------------------------------
#define FL_KV_OFF   9216
#define FL_SMEM_BYTES (46080 * 2)

__global__ __launch_bounds__(256, 2) void flash_kernel(
    const __half* __restrict__ Q, const __half* __restrict__ K,
    const __half* __restrict__ V, __half* __restrict__ O)
{
    extern __shared__ __half sm[];

    const int tid  = threadIdx.x;
    const int w    = tid >> 5, lane = tid & 31;
    const int g    = lane >> 2, tg = lane & 3;
    const int bh   = blockIdx.y;
    const int q0   = blockIdx.x * 128;
    const int b    = bh >> 4, h = bh & 15;

    const int lrow = (lane & 7) + ((lane >> 3) & 1) * 8;
    const int lcol = ((lane >> 4) & 1) * 8;
    const int brow = (lane & 7) + ((lane >> 4) & 1) * 8;
    const int bcol = ((lane >> 3) & 1) * 8;

    const __half* Qp = Q + (size_t)bh * NSEQ * HD;
    const __half* Kp = K + (size_t)bh * NSEQ * HD;
    const __half* Vp = V + (size_t)bh * NSEQ * HD;

    auto issue = [&](int j) {
        __half* Kb = sm + FL_KV_OFF + (j & 1) * 18432;
        __half* Vb = Kb + 9216;
        #pragma unroll
        for (int i = 0; i < 4; i++) {
            int id = tid + i * 256;
            int r = id >> 3, c = (id & 7) * 8;
            size_t go = (size_t)(j * 128 + r) * HD + c;
            cp16(Kb + r * 72 + c, Kp + go);
            cp16(Vb + r * 72 + c, Vp + go);
        }
        CP_COMMIT();
    };

    issue(0);

    #pragma unroll
    for (int i = 0; i < 4; i++) {
        int id = tid + i * 256;
        int r = id >> 3, c = (id & 7) * 8;
        *(uint4*)(sm + r * 72 + c) = *(const uint4*)(Qp + (size_t)(q0 + r) * HD + c);
    }
    __syncthreads();
    unsigned qf[4][4];
    #pragma unroll
    for (int ks = 0; ks < 4; ks++)
        ldsm4(qf[ks][0], qf[ks][1], qf[ks][2], qf[ks][3],
              sm + (w * 16 + lrow) * 72 + ks * 16 + lcol);

    float m0 = -1e30f, m1 = -1e30f, l0 = 0.f, l1 = 0.f;
    float oa[8][4] = {};

    for (int j = 0; j < 16; j++) {
        if (j < 15) { issue(j + 1); CP_WAIT(1); }
        else        { CP_WAIT(0); }
        __syncthreads();

        const __half* Ks = sm + FL_KV_OFF + (j & 1) * 18432;
        const __half* Vs = Ks + 9216;

        #pragma unroll
        for (int half = 0; half < 2; half++) {
            // ---- S = Q K^T chunk (16 q rows x 64 kv) ----
            float s[8][4];
            #pragma unroll
            for (int ni = 0; ni < 8; ni++)
                s[ni][0] = s[ni][1] = s[ni][2] = s[ni][3] = 0.f;
            #pragma unroll
            for (int ks = 0; ks < 4; ks++) {
                #pragma unroll
                for (int n2 = 0; n2 < 4; n2++) {
                    unsigned r0, r1, r2, r3;
                    ldsm4(r0, r1, r2, r3,
                          Ks + (half * 64 + n2 * 16 + brow) * 72 + ks * 16 + bcol);
                    mma16(s[2*n2],     qf[ks], r0, r1);
                    mma16(s[2*n2 + 1], qf[ks], r2, r3);
                }
            }

            // ---- online softmax (chunk) ----
            float mt0 = -1e30f, mt1 = -1e30f;
            #pragma unroll
            for (int ni = 0; ni < 8; ni++) {
                s[ni][0] *= 0.125f; s[ni][1] *= 0.125f;
                s[ni][2] *= 0.125f; s[ni][3] *= 0.125f;
                mt0 = fmaxf(mt0, fmaxf(s[ni][0], s[ni][1]));
                mt1 = fmaxf(mt1, fmaxf(s[ni][2], s[ni][3]));
            }
            mt0 = fmaxf(mt0, __shfl_xor_sync(~0u, mt0, 1));
            mt0 = fmaxf(mt0, __shfl_xor_sync(~0u, mt0, 2));
            mt1 = fmaxf(mt1, __shfl_xor_sync(~0u, mt1, 1));
            mt1 = fmaxf(mt1, __shfl_xor_sync(~0u, mt1, 2));
            float m0n = fmaxf(m0, mt0), m1n = fmaxf(m1, mt1);
            float c0 = __expf(m0 - m0n), c1 = __expf(m1 - m1n);
            float rs0 = 0.f, rs1 = 0.f;
            #pragma unroll
            for (int ni = 0; ni < 8; ni++) {
                s[ni][0] = __expf(s[ni][0] - m0n);
                s[ni][1] = __expf(s[ni][1] - m0n);
                s[ni][2] = __expf(s[ni][2] - m1n);
                s[ni][3] = __expf(s[ni][3] - m1n);
                rs0 += s[ni][0] + s[ni][1];
                rs1 += s[ni][2] + s[ni][3];
            }
            rs0 += __shfl_xor_sync(~0u, rs0, 1); rs0 += __shfl_xor_sync(~0u, rs0, 2);
            rs1 += __shfl_xor_sync(~0u, rs1, 1); rs1 += __shfl_xor_sync(~0u, rs1, 2);
            l0 = l0 * c0 + rs0; l1 = l1 * c1 + rs1;
            m0 = m0n; m1 = m1n;
            #pragma unroll
            for (int ni = 0; ni < 8; ni++) {
                oa[ni][0] *= c0; oa[ni][1] *= c0;
                oa[ni][2] *= c1; oa[ni][3] *= c1;
            }

            // ---- O += P V chunk ----
            #pragma unroll
            for (int c = 0; c < 4; c++) {
                unsigned a[4];
                a[0] = h2bits(s[2*c][0],     s[2*c][1]);
                a[1] = h2bits(s[2*c][2],     s[2*c][3]);
                a[2] = h2bits(s[2*c + 1][0], s[2*c + 1][1]);
                a[3] = h2bits(s[2*c + 1][2], s[2*c + 1][3]);
                #pragma unroll
                for (int n2 = 0; n2 < 4; n2++) {
                    unsigned r0, r1, r2, r3;
                    ldsm4t(r0, r1, r2, r3,
                           Vs + (half * 64 + c * 16 + lrow) * 72 + n2 * 16 + lcol);
                    mma16(oa[2*n2],     a, r0, r1);
                    mma16(oa[2*n2 + 1], a, r2, r3);
                }
            }
        }
        __syncthreads();
    }

    // ---- epilogue ----
    float i0 = 1.f / l0, i1 = 1.f / l1;
    int r0 = q0 + w * 16 + g, r1 = r0 + 8;
    __half* Op = O + ((size_t)b * NSEQ) * DIM + h * HD;
    #pragma unroll
    for (int ni = 0; ni < 8; ni++) {
        int cb = ni * 8 + 2 * tg;
        *(__half2*)(Op + (size_t)r0 * DIM + cb) =
            __floats2half2_rn(oa[ni][0] * i0, oa[ni][1] * i0);
        *(__half2*)(Op + (size_t)r1 * DIM + cb) =
            __floats2half2_rn(oa[ni][2] * i1, oa[ni][3] * i1);
    }
}

// ---------------------------------------------------------------------------
// RoPE + QKV split (half in, half out)
// ---------------------------------------------------------------------------
__global__ void rope_split_kernel(const __half* __restrict__ qkv,
                                  const float* __restrict__ enc)
{
    size_t idx = (size_t)blockIdx.x * blockDim.x + threadIdx.x;
    const size_t total = (size_t)BB * NH * NSEQ * (HD / 2);
    if (idx >= total) return;
    int pair = idx & 31;
    size_t t = idx >> 5;
    int n = t & (NSEQ - 1); t >>= 11;
    int h = t & (NH - 1);
    int b = (int)(t >> 4);

    const __half* src = qkv + ((size_t)(b * NSEQ + n) * (3 * DIM)
                               + h * (HD * 3) + pair * 6);
    float q0 = __half2float(src[0]), k0 = __half2float(src[1]);
    float v0 = __half2float(src[2]), q1 = __half2float(src[3]);
    float k1 = __half2float(src[4]), v1 = __half2float(src[5]);

    const float* e0 = enc + (size_t)n * HD + pair * 2;
    const float* e1 = enc + (size_t)NSEQ * HD + (size_t)n * HD + pair * 2;
    float f00 = e0[0], f01 = e0[1], f10 = e1[0], f11 = e1[1];

    size_t o = ((size_t)(b * NH + h) * NSEQ + n) * HD + pair * 2;
    *(__half2*)(g_q + o) = __floats2half2_rn(q0 * f00 - q1 * f10,
                                             q1 * f01 + q0 * f11);
    *(__half2*)(g_k + o) = __floats2half2_rn(k0 * f00 - k1 * f10,
                                             k1 * f01 + k0 * f11);
    *(__half2*)(g_v + o) = __floats2half2_rn(v0, v1);
}

// LayerNorm (2048) + exact GELU, in place on g_h (half).
__global__ __launch_bounds__(256) void ln_gelu_kernel(const float* __restrict__ scale,
                                                      const float* __restrict__ bias)
{
    const int n = 2 * DIM;
    __half* p = g_h + (size_t)blockIdx.x * n;
    const int tid = threadIdx.x;
    __shared__ float s8a[8], s8b[8];

    float s = 0.f, sq = 0.f;
    for (int i = tid; i < n / 2; i += 256) {
        float2 v = __half22float2(*(__half2*)(p + i * 2));
        s += v.x + v.y;
        sq = fmaf(v.x, v.x, fmaf(v.y, v.y, sq));
    }
    #pragma unroll
    for (int o = 16; o > 0; o >>= 1) {
        s  += __shfl_xor_sync(~0u, s, o);
        sq += __shfl_xor_sync(~0u, sq, o);
    }
    if ((tid & 31) == 0) { s8a[tid >> 5] = s; s8b[tid >> 5] = sq; }
    __syncthreads();
    s = 0.f; sq = 0.f;
    #pragma unroll
    for (int i = 0; i < 8; i++) { s += s8a[i]; sq += s8b[i]; }
    float mu = s / n;
    float var = sq / n - mu * mu;
    float rstd = rsqrtf(var + 1e-5f);

    for (int i = tid; i < n / 2; i += 256) {
        float2 v = __half22float2(*(__half2*)(p + i * 2));
        float a = (v.x - mu) * rstd * scale[i * 2]     + bias[i * 2];
        float c = (v.y - mu) * rstd * scale[i * 2 + 1] + bias[i * 2 + 1];
        a = 0.5f * a * (1.f + erff(a * 0.70710678118654752f));
        c = 0.5f * c * (1.f + erff(c * 0.70710678118654752f));
        *(__half2*)(p + i * 2) = __floats2half2_rn(a, c);
    }
}

// ---------------------------------------------------------------------------
// Host
// ---------------------------------------------------------------------------
static inline void* sym(const void* s)
{
    void* p = nullptr;
    cudaGetSymbolAddress(&p, s);
    return p;
}

extern "C" void kernel_launch(void* const* d_in, const int* in_sizes, int n_in,
                              void* d_out, int out_size)
{
    const float* x       = (const float*)d_in[0];
    const float* enc     = (const float*)d_in[1];
    const float* Wqkv_w  = (const float*)d_in[2];
    const float* Wqkv_b  = (const float*)d_in[3];
    const float* out_w   = (const float*)d_in[4];
    const float* out_b   = (const float*)d_in[5];
    const float* ffn0_w  = (const float*)d_in[6];
    const float* ffn0_b  = (const float*)d_in[7];
    const float* ln_s    = (const float*)d_in[8];
    const float* ln_b    = (const float*)d_in[9];
    const float* ffn3_w  = (const float*)d_in[10];
    const float* ffn3_b  = (const float*)d_in[11];
    float* out = (float*)d_out;

    __half* xr     = (__half*)sym(g_xr);
    __half* qkv    = (__half*)sym(g_qkv);
    __half* q      = (__half*)sym(g_q);
    __half* k      = (__half*)sym(g_k);
    __half* v      = (__half*)sym(g_v);
    __half* msgin  = (__half*)sym(g_msgin);
    __half* hbuf   = (__half*)sym(g_h);
    __half* wqkvT  = (__half*)sym(g_wqkvT);
    __half* woutNT = (__half*)sym(g_woutNT);
    __half* w0T    = (__half*)sym(g_w0T);
    __half* wf     = (__half*)sym(g_wf);
    __half* w3T    = (__half*)sym(g_w3T);
    float*  b0f    = (float*)sym(g_b0f);

    static cudaStream_t s2 = nullptr;
    static cudaEvent_t evFork = nullptr, evJoin = nullptr;
    static bool attr_done = false;
    if (!attr_done) {
        cudaFuncSetAttribute(flash_kernel,
            cudaFuncAttributeMaxDynamicSharedMemorySize, FL_SMEM_BYTES);
        cudaFuncSetAttribute(hgemm<0>,
            cudaFuncAttributeMaxDynamicSharedMemorySize, GEMM_SMEM);
        cudaFuncSetAttribute(hgemm<1>,
            cudaFuncAttributeMaxDynamicSharedMemorySize, GEMM_SMEM);
        cudaStreamCreateWithFlags(&s2, cudaStreamNonBlocking);
        cudaEventCreateWithFlags(&evFork, cudaEventDisableTiming);
        cudaEventCreateWithFlags(&evJoin, cudaEventDisableTiming);
        attr_done = true;
    }

    // ---- fork: FFN-weight prep on side stream (needed only at step 4) ----
    cudaEventRecord(evFork, 0);
    cudaStreamWaitEvent(s2, evFork, 0);

    wt_round_T<<<dim3(2 * DIM / 32, 2 * DIM / 32), dim3(32, 8), 0, s2>>>(
        ffn0_w, w0T, 2 * DIM, 2 * DIM);
    wt_round_T<<<dim3(DIM / 32, 2 * DIM / 32), dim3(32, 8), 0, s2>>>(
        ffn3_w, w3T, 2 * DIM, DIM);
    round_copy<<<(DIM * DIM / 2 + 255) / 256, 256, 0, s2>>>(
        out_w, woutNT, (size_t)DIM * DIM / 2);
    hgemm<1><<<dim3(DIM / 128, 2 * DIM / 128), 256, GEMM_SMEM, s2>>>(
        w0T + DIM, nullptr, woutNT, nullptr, nullptr, wf,
        DIM, DIM, 2 * DIM, 0, DIM);
    copy_wf<<<((size_t)(2 * DIM) * DIM / 2 + 255) / 256, 256, 0, s2>>>();
    bias_fuse<<<2 * DIM / 256, 256, 0, s2>>>(ffn0_b, out_b, ffn0_w);

    cudaEventRecord(evJoin, s2);

    // ---- main stream: QKV chain ----
    wt_round_T<<<dim3(3 * DIM / 32, DIM / 32), dim3(32, 8)>>>(Wqkv_w, wqkvT, DIM, 3 * DIM);
    round_copy<<<((size_t)MTOK * DIM / 2 + 255) / 256, 256>>>(x, xr, (size_t)MTOK * DIM / 2);

    hgemm<1><<<dim3(3 * DIM / 128, MTOK / 128), 256, GEMM_SMEM>>>(
        xr, nullptr, wqkvT, Wqkv_b, nullptr, qkv, DIM, DIM, DIM, 0, 3 * DIM);

    {
        size_t total = (size_t)BB * NH * NSEQ * (HD / 2);
        rope_split_kernel<<<(unsigned)((total + 255) / 256), 256>>>(qkv, enc);
    }

    flash_kernel<<<dim3(NSEQ / 128, BHN), 256, FL_SMEM_BYTES>>>(
        q, k, v, msgin);

    // ---- join before FFN0 (uses w0T/b0f) ----
    cudaStreamWaitEvent(0, evJoin, 0);

    hgemm<1><<<dim3(2 * DIM / 128, MTOK / 128), 256, GEMM_SMEM>>>(
        xr, msgin, w0T, b0f, nullptr, hbuf, 2 * DIM, DIM, DIM, DIM, 2 * DIM);

    ln_gelu_kernel<<<MTOK, 256>>>(ln_s, ln_b);

    hgemm<0><<<dim3(DIM / 128, MTOK / 128), 256, GEMM_SMEM>>>(
        hbuf, nullptr, w3T, ffn3_b, x, out, 2 * DIM, 2 * DIM, 2 * DIM, 0, DIM);
}